// round 1
// baseline (speedup 1.0000x reference)
#include <cuda_runtime.h>
#include <math.h>

// Problem constants (fixed shapes from setup_inputs)
#define Bb 8
#define NN 1024
#define CC 544
#define JJ 17
#define FF 32
#define HH 8
#define HD 68
#define QC 1632   // 3*C

// -------- scratch (static device globals; no dynamic allocation) --------
__device__ float g_xr [(size_t)Bb * NN * CC];   // joint-LN'd x
__device__ float g_sc [(size_t)Bb * NN * JJ];   // pooling scores
__device__ float g_w  [(size_t)Bb * NN * JJ];   // softmax-over-N weights
__device__ float g_xp [(size_t)Bb * NN * CC];   // pooled + LN'd
__device__ float g_qkv[(size_t)Bb * NN * QC];   // qkv, layout [b,n, s*C + h*HD + d]
__device__ float g_ao [(size_t)Bb * NN * CC];   // attention output [b,n, h*HD+d]

__device__ __forceinline__ float wsum(float v) {
#pragma unroll
    for (int o = 16; o > 0; o >>= 1) v += __shfl_xor_sync(0xffffffffu, v, o);
    return v;
}
__device__ __forceinline__ float wmax(float v) {
#pragma unroll
    for (int o = 16; o > 0; o >>= 1) v = fmaxf(v, __shfl_xor_sync(0xffffffffu, v, o));
    return v;
}

// ---------------------------------------------------------------------------
// Kernel 1: per-joint layernorm (F=32) + attention-pooling scores
// grid = B*N blocks, 544 threads (17 warps = 17 joints, lane = feature)
// ---------------------------------------------------------------------------
__global__ void k_ln_joint(const float* __restrict__ x,
                           const float* __restrict__ ng,
                           const float* __restrict__ nb,
                           const float* __restrict__ apw,
                           const float* __restrict__ apb) {
    int bn = blockIdx.x;
    int j = threadIdx.x >> 5;
    int f = threadIdx.x & 31;

    float v = x[(size_t)bn * CC + j * FF + f];
    float mu = wsum(v) * (1.0f / FF);
    float d = v - mu;
    float var = wsum(d * d) * (1.0f / FF);
    float xn = d * rsqrtf(var + 1e-5f) * ng[f] + nb[f];
    g_xr[(size_t)bn * CC + j * FF + f] = xn;

    float sc = wsum(xn * apw[f]);
    if (f == 0) g_sc[(size_t)bn * JJ + j] = sc + apb[0];
}

// ---------------------------------------------------------------------------
// Kernel 2: softmax over the SEQUENCE axis N, per (b, joint). 136 blocks.
// ---------------------------------------------------------------------------
__global__ void k_softmax_seq() {
    int bj = blockIdx.x;
    int b = bj / JJ, j = bj - b * JJ;
    int tid = threadIdx.x;      // 256 threads, 4 elems each
    const float* base = g_sc + (size_t)b * NN * JJ + j;

    float v[4];
#pragma unroll
    for (int i = 0; i < 4; i++) v[i] = base[(size_t)(tid + i * 256) * JJ];

    __shared__ float red[8];
    __shared__ float bc;
    int wid = tid >> 5, lane = tid & 31;

    float mx = fmaxf(fmaxf(v[0], v[1]), fmaxf(v[2], v[3]));
    mx = wmax(mx);
    if (lane == 0) red[wid] = mx;
    __syncthreads();
    if (tid == 0) {
        float m = red[0];
        for (int i = 1; i < 8; i++) m = fmaxf(m, red[i]);
        bc = m;
    }
    __syncthreads();
    mx = bc;
    __syncthreads();

    float se = 0.f;
#pragma unroll
    for (int i = 0; i < 4; i++) { v[i] = __expf(v[i] - mx); se += v[i]; }
    se = wsum(se);
    if (lane == 0) red[wid] = se;
    __syncthreads();
    if (tid == 0) {
        float s = 0.f;
        for (int i = 0; i < 8; i++) s += red[i];
        bc = 1.0f / s;
    }
    __syncthreads();
    float inv = bc;

    float* wbase = g_w + (size_t)b * NN * JJ + j;
#pragma unroll
    for (int i = 0; i < 4; i++) wbase[(size_t)(tid + i * 256) * JJ] = v[i] * inv;
}

// ---------------------------------------------------------------------------
// Kernel 3: xp = xr * w, then layernorm over C=544. grid = B*N, 544 threads.
// ---------------------------------------------------------------------------
__global__ void k_pool_ln(const float* __restrict__ g2,
                          const float* __restrict__ b2) {
    int bn = blockIdx.x;
    int c = threadIdx.x;
    int wid = c >> 5, lane = c & 31;
    __shared__ float red[17];
    __shared__ float bc0, bc1;

    float v = g_xr[(size_t)bn * CC + c] * g_w[(size_t)bn * JJ + (c >> 5)];

    float s = wsum(v);
    if (lane == 0) red[wid] = s;
    __syncthreads();
    if (wid == 0) {
        float t = (lane < 17) ? red[lane] : 0.f;
        t = wsum(t);
        if (lane == 0) bc0 = t * (1.0f / CC);
    }
    __syncthreads();
    float mu = bc0;
    float d = v - mu;

    float s2 = wsum(d * d);
    if (lane == 0) red[wid] = s2;
    __syncthreads();
    if (wid == 0) {
        float t = (lane < 17) ? red[lane] : 0.f;
        t = wsum(t);
        if (lane == 0) bc1 = t * (1.0f / CC);
    }
    __syncthreads();
    float var = bc1;

    g_xp[(size_t)bn * CC + c] = d * rsqrtf(var + 1e-5f) * g2[c] + b2[c];
}

// ---------------------------------------------------------------------------
// Generic NT SGEMM: C[M,Nn] = A[M,K] @ B[Nn,K]^T (+ bias)
// 64x64 tile, k-step 16, 256 threads, 4x4 per thread.
// M and K assumed multiples of 64/16; Nn guarded.
// ---------------------------------------------------------------------------
__device__ __forceinline__ void sgemm_body(const float* __restrict__ A,
                                           const float* __restrict__ Bm,
                                           float* __restrict__ Cm,
                                           int M, int Nn, int K,
                                           const float* __restrict__ bias) {
    __shared__ float As[16][68];
    __shared__ float Bs[16][68];
    int tid = threadIdx.x;
    int tx = tid & 15, ty = tid >> 4;
    int m0 = blockIdx.y * 64, n0 = blockIdx.x * 64;
    int lr = tid >> 2;
    int lc = (tid & 3) << 2;

    float acc[4][4];
#pragma unroll
    for (int i = 0; i < 4; i++)
#pragma unroll
        for (int jj = 0; jj < 4; jj++) acc[i][jj] = 0.f;

    for (int k0 = 0; k0 < K; k0 += 16) {
        float4 av = *(const float4*)(A + (size_t)(m0 + lr) * K + k0 + lc);
        float4 bv = make_float4(0.f, 0.f, 0.f, 0.f);
        if (n0 + lr < Nn)
            bv = *(const float4*)(Bm + (size_t)(n0 + lr) * K + k0 + lc);
        __syncthreads();
        As[lc + 0][lr] = av.x; As[lc + 1][lr] = av.y;
        As[lc + 2][lr] = av.z; As[lc + 3][lr] = av.w;
        Bs[lc + 0][lr] = bv.x; Bs[lc + 1][lr] = bv.y;
        Bs[lc + 2][lr] = bv.z; Bs[lc + 3][lr] = bv.w;
        __syncthreads();
#pragma unroll
        for (int k = 0; k < 16; k++) {
            float4 a = *(const float4*)(&As[k][ty * 4]);
            float4 b = *(const float4*)(&Bs[k][tx * 4]);
            acc[0][0] += a.x * b.x; acc[0][1] += a.x * b.y; acc[0][2] += a.x * b.z; acc[0][3] += a.x * b.w;
            acc[1][0] += a.y * b.x; acc[1][1] += a.y * b.y; acc[1][2] += a.y * b.z; acc[1][3] += a.y * b.w;
            acc[2][0] += a.z * b.x; acc[2][1] += a.z * b.y; acc[2][2] += a.z * b.z; acc[2][3] += a.z * b.w;
            acc[3][0] += a.w * b.x; acc[3][1] += a.w * b.y; acc[3][2] += a.w * b.z; acc[3][3] += a.w * b.w;
        }
    }

#pragma unroll
    for (int i = 0; i < 4; i++) {
        int mm = m0 + ty * 4 + i;
        float* crow = Cm + (size_t)mm * Nn;
#pragma unroll
        for (int jj = 0; jj < 4; jj++) {
            int nn = n0 + tx * 4 + jj;
            if (nn < Nn) crow[nn] = acc[i][jj] + (bias ? bias[nn] : 0.f);
        }
    }
}

__global__ void k_gemm_qkv(const float* __restrict__ w) {
    sgemm_body(g_xp, w, g_qkv, Bb * NN, QC, CC, nullptr);
}
__global__ void k_gemm_proj(const float* __restrict__ w,
                            const float* __restrict__ bias,
                            float* __restrict__ out) {
    sgemm_body(g_ao, w, out, Bb * NN, CC, CC, bias);
}

// ---------------------------------------------------------------------------
// Kernel 5: position-scaled attention, online softmax.
// grid = (N/128, H, B), 128 threads. Thread = one q row (68-reg accumulator).
// Key/Value staged in smem in 32-key tiles.
// ---------------------------------------------------------------------------
__global__ void __launch_bounds__(128) k_attn(const float* __restrict__ sf_ptr) {
    int b = blockIdx.z, h = blockIdx.y, qt = blockIdx.x;
    int tid = threadIdx.x;

    __shared__ float sm[8704];          // stage Q (128x68), then K/V tiles

    // stage Q tile coalesced, then copy own row into regs
    for (int idx = tid; idx < 128 * HD; idx += 128) {
        int r = idx / HD, d = idx - r * HD;
        sm[idx] = g_qkv[((size_t)(b * NN + qt * 128 + r)) * QC + h * HD + d];
    }
    __syncthreads();
    float q[HD];
#pragma unroll
    for (int d = 0; d < HD; d++) q[d] = sm[tid * HD + d];
    __syncthreads();

    float* Ks = sm;                 // [32][68]
    float* Vs = sm + 32 * HD;       // [32][68]
    float* ps = sm + 64 * HD;       // [32]

    float acc[HD];
#pragma unroll
    for (int d = 0; d < HD; d++) acc[d] = 0.f;
    float m = -1e30f, l = 0.f;

    const float sf = sf_ptr[0];
    const float scl = rsqrtf((float)HD);

    for (int kt = 0; kt < NN / 32; kt++) {
        int kbase = kt * 32;
        for (int idx = tid; idx < 32 * HD; idx += 128) {
            int r = idx / HD, d = idx - r * HD;
            size_t off = ((size_t)(b * NN + kbase + r)) * QC + h * HD + d;
            Ks[idx] = g_qkv[off + CC];        // K
            Vs[idx] = g_qkv[off + 2 * CC];    // V
        }
        if (tid < 32) {
            float pos = (float)(kbase + tid) * (1.0f / (NN - 1));
            float dd = pos - 0.5f;
            ps[tid] = scl * __expf(-sf * dd * dd);
        }
        __syncthreads();

        float s[32];
        float tmax = -1e30f;
#pragma unroll
        for (int jj = 0; jj < 32; jj++) {
            const float4* k4 = (const float4*)(Ks + jj * HD);
            float a = 0.f;
#pragma unroll
            for (int dd = 0; dd < HD / 4; dd++) {
                float4 kv = k4[dd];
                a += q[dd * 4 + 0] * kv.x + q[dd * 4 + 1] * kv.y
                   + q[dd * 4 + 2] * kv.z + q[dd * 4 + 3] * kv.w;
            }
            a *= ps[jj];
            s[jj] = a;
            tmax = fmaxf(tmax, a);
        }

        float mnew = fmaxf(m, tmax);
        float corr = __expf(m - mnew);
        m = mnew;
        float psum = 0.f;
#pragma unroll
        for (int jj = 0; jj < 32; jj++) { s[jj] = __expf(s[jj] - mnew); psum += s[jj]; }
        l = l * corr + psum;
#pragma unroll
        for (int d = 0; d < HD; d++) acc[d] *= corr;
#pragma unroll
        for (int jj = 0; jj < 32; jj++) {
            const float4* v4 = (const float4*)(Vs + jj * HD);
            float pj = s[jj];
#pragma unroll
            for (int dd = 0; dd < HD / 4; dd++) {
                float4 vv = v4[dd];
                acc[dd * 4 + 0] += pj * vv.x; acc[dd * 4 + 1] += pj * vv.y;
                acc[dd * 4 + 2] += pj * vv.z; acc[dd * 4 + 3] += pj * vv.w;
            }
        }
        __syncthreads();
    }

    float inv = 1.0f / l;
    int nq = qt * 128 + tid;
    float* outp = g_ao + ((size_t)(b * NN + nq)) * CC + h * HD;
#pragma unroll
    for (int d = 0; d < HD; d++) outp[d] = acc[d] * inv;
}

// ---------------------------------------------------------------------------
extern "C" void kernel_launch(void* const* d_in, const int* in_sizes, int n_in,
                              void* d_out, int out_size) {
    const float* x       = (const float*)d_in[0];
    const float* norm_g  = (const float*)d_in[1];
    const float* norm_b  = (const float*)d_in[2];
    const float* ap_w    = (const float*)d_in[3];
    const float* ap_b    = (const float*)d_in[4];
    const float* norm2_g = (const float*)d_in[5];
    const float* norm2_b = (const float*)d_in[6];
    const float* qkv_w   = (const float*)d_in[7];
    const float* proj_w  = (const float*)d_in[8];
    const float* proj_b  = (const float*)d_in[9];
    const float* scaling = (const float*)d_in[10];
    float* out = (float*)d_out;

    k_ln_joint<<<Bb * NN, CC>>>(x, norm_g, norm_b, ap_w, ap_b);
    k_softmax_seq<<<Bb * JJ, 256>>>();
    k_pool_ln<<<Bb * NN, CC>>>(norm2_g, norm2_b);
    k_gemm_qkv<<<dim3((QC + 63) / 64, (Bb * NN) / 64), 256>>>(qkv_w);
    k_attn<<<dim3(NN / 128, HH, Bb), 128>>>(scaling);
    k_gemm_proj<<<dim3((CC + 63) / 64, (Bb * NN) / 64), 256>>>(proj_w, proj_b, out);
}

// round 2
// speedup vs baseline: 1.1583x; 1.1583x over previous
#include <cuda_runtime.h>
#include <math.h>

typedef unsigned long long ull;

// Problem constants (fixed shapes)
#define Bb 8
#define NN 1024
#define CC 544
#define JJ 17
#define FF 32
#define HH 8
#define HD 68
#define QC 1632   // 3*C

// packed f32x2 ops (sm_103a; ptxas never auto-fuses — PTX only)
#define FMA2(d,a,b,c) asm("fma.rn.f32x2 %0, %1, %2, %3;" : "=l"(d) : "l"(a), "l"(b), "l"(c))
#define MUL2(d,a,b)   asm("mul.rn.f32x2 %0, %1, %2;"     : "=l"(d) : "l"(a), "l"(b))
#define PACK2(d,x)    asm("mov.b64 %0, {%1, %1};"        : "=l"(d) : "f"(x))
__device__ __forceinline__ float2 unpk(ull v) {
    float2 r; asm("mov.b64 {%0, %1}, %2;" : "=f"(r.x), "=f"(r.y) : "l"(v)); return r;
}

// -------- scratch --------
__device__ float g_xr [(size_t)Bb * NN * CC];
__device__ float g_sc [(size_t)Bb * NN * JJ];
__device__ float g_w  [(size_t)Bb * NN * JJ];
__device__ float g_xp [(size_t)Bb * NN * CC];
__device__ float g_qkv[(size_t)Bb * NN * QC];
__device__ float g_ao [(size_t)Bb * NN * CC];

__device__ __forceinline__ float wsum(float v) {
#pragma unroll
    for (int o = 16; o > 0; o >>= 1) v += __shfl_xor_sync(0xffffffffu, v, o);
    return v;
}
__device__ __forceinline__ float wmax(float v) {
#pragma unroll
    for (int o = 16; o > 0; o >>= 1) v = fmaxf(v, __shfl_xor_sync(0xffffffffu, v, o));
    return v;
}

// ---------------------------------------------------------------------------
// Kernel 1: per-joint layernorm + pooling scores
// ---------------------------------------------------------------------------
__global__ void k_ln_joint(const float* __restrict__ x,
                           const float* __restrict__ ng,
                           const float* __restrict__ nb,
                           const float* __restrict__ apw,
                           const float* __restrict__ apb) {
    int bn = blockIdx.x;
    int j = threadIdx.x >> 5;
    int f = threadIdx.x & 31;

    float v = x[(size_t)bn * CC + j * FF + f];
    float mu = wsum(v) * (1.0f / FF);
    float d = v - mu;
    float var = wsum(d * d) * (1.0f / FF);
    float xn = d * rsqrtf(var + 1e-5f) * ng[f] + nb[f];
    g_xr[(size_t)bn * CC + j * FF + f] = xn;

    float sc = wsum(xn * apw[f]);
    if (f == 0) g_sc[(size_t)bn * JJ + j] = sc + apb[0];
}

// ---------------------------------------------------------------------------
// Kernel 2: softmax over sequence axis N per (b, joint)
// ---------------------------------------------------------------------------
__global__ void k_softmax_seq() {
    int bj = blockIdx.x;
    int b = bj / JJ, j = bj - b * JJ;
    int tid = threadIdx.x;
    const float* base = g_sc + (size_t)b * NN * JJ + j;

    float v[4];
#pragma unroll
    for (int i = 0; i < 4; i++) v[i] = base[(size_t)(tid + i * 256) * JJ];

    __shared__ float red[8];
    __shared__ float bc;
    int wid = tid >> 5, lane = tid & 31;

    float mx = fmaxf(fmaxf(v[0], v[1]), fmaxf(v[2], v[3]));
    mx = wmax(mx);
    if (lane == 0) red[wid] = mx;
    __syncthreads();
    if (tid == 0) {
        float m = red[0];
        for (int i = 1; i < 8; i++) m = fmaxf(m, red[i]);
        bc = m;
    }
    __syncthreads();
    mx = bc;
    __syncthreads();

    float se = 0.f;
#pragma unroll
    for (int i = 0; i < 4; i++) { v[i] = __expf(v[i] - mx); se += v[i]; }
    se = wsum(se);
    if (lane == 0) red[wid] = se;
    __syncthreads();
    if (tid == 0) {
        float s = 0.f;
        for (int i = 0; i < 8; i++) s += red[i];
        bc = 1.0f / s;
    }
    __syncthreads();
    float inv = bc;

    float* wbase = g_w + (size_t)b * NN * JJ + j;
#pragma unroll
    for (int i = 0; i < 4; i++) wbase[(size_t)(tid + i * 256) * JJ] = v[i] * inv;
}

// ---------------------------------------------------------------------------
// Kernel 3: pool + layernorm over C
// ---------------------------------------------------------------------------
__global__ void k_pool_ln(const float* __restrict__ g2,
                          const float* __restrict__ b2) {
    int bn = blockIdx.x;
    int c = threadIdx.x;
    int wid = c >> 5, lane = c & 31;
    __shared__ float red[17];
    __shared__ float bc0, bc1;

    float v = g_xr[(size_t)bn * CC + c] * g_w[(size_t)bn * JJ + (c >> 5)];

    float s = wsum(v);
    if (lane == 0) red[wid] = s;
    __syncthreads();
    if (wid == 0) {
        float t = (lane < 17) ? red[lane] : 0.f;
        t = wsum(t);
        if (lane == 0) bc0 = t * (1.0f / CC);
    }
    __syncthreads();
    float mu = bc0;
    float d = v - mu;

    float s2 = wsum(d * d);
    if (lane == 0) red[wid] = s2;
    __syncthreads();
    if (wid == 0) {
        float t = (lane < 17) ? red[lane] : 0.f;
        t = wsum(t);
        if (lane == 0) bc1 = t * (1.0f / CC);
    }
    __syncthreads();
    float var = bc1;

    g_xp[(size_t)bn * CC + c] = d * rsqrtf(var + 1e-5f) * g2[c] + b2[c];
}

// ---------------------------------------------------------------------------
// FFMA2 SGEMM: C[M,Nn] = A[M,K] @ B[Nn,K]^T (+ bias)
// 128x64 tile, BK=16, 256 threads, per-thread 8x4 via f32x2 (m-paired acc).
// ---------------------------------------------------------------------------
#define BM 128
#define BN 64
#define BK 16

__global__ void __launch_bounds__(256) k_sgemm(const float* __restrict__ A,
                                               const float* __restrict__ Bm,
                                               float* __restrict__ Cm,
                                               int Nn, int K,
                                               const float* __restrict__ bias) {
    __shared__ float As[BK][BM + 4];   // transposed: [k][m], stride 132
    __shared__ float Bs[BK][BN + 4];   // transposed: [k][n], stride 68
    int tid = threadIdx.x;
    int tx = tid & 15, ty = tid >> 4;
    int m0 = blockIdx.y * BM, n0 = blockIdx.x * BN;
    int lr = tid >> 2;            // 0..63
    int c4 = (tid & 3) * 4;       // 0,4,8,12

    ull acc[4][4];
#pragma unroll
    for (int i = 0; i < 4; i++)
#pragma unroll
        for (int j = 0; j < 4; j++) acc[i][j] = 0ull;

    for (int k0 = 0; k0 < K; k0 += BK) {
        float4 av0 = *(const float4*)(A + (size_t)(m0 + lr) * K + k0 + c4);
        float4 av1 = *(const float4*)(A + (size_t)(m0 + 64 + lr) * K + k0 + c4);
        float4 bv = make_float4(0.f, 0.f, 0.f, 0.f);
        if (n0 + lr < Nn)
            bv = *(const float4*)(Bm + (size_t)(n0 + lr) * K + k0 + c4);
        __syncthreads();
        As[c4 + 0][lr] = av0.x; As[c4 + 1][lr] = av0.y;
        As[c4 + 2][lr] = av0.z; As[c4 + 3][lr] = av0.w;
        As[c4 + 0][64 + lr] = av1.x; As[c4 + 1][64 + lr] = av1.y;
        As[c4 + 2][64 + lr] = av1.z; As[c4 + 3][64 + lr] = av1.w;
        Bs[c4 + 0][lr] = bv.x; Bs[c4 + 1][lr] = bv.y;
        Bs[c4 + 2][lr] = bv.z; Bs[c4 + 3][lr] = bv.w;
        __syncthreads();
#pragma unroll
        for (int k = 0; k < BK; k++) {
            ulonglong2 a01 = *(const ulonglong2*)&As[k][ty * 8];
            ulonglong2 a23 = *(const ulonglong2*)&As[k][ty * 8 + 4];
            float4 b = *(const float4*)&Bs[k][tx * 4];
            ull am[4] = { a01.x, a01.y, a23.x, a23.y };
            ull bd[4];
            PACK2(bd[0], b.x); PACK2(bd[1], b.y);
            PACK2(bd[2], b.z); PACK2(bd[3], b.w);
#pragma unroll
            for (int i = 0; i < 4; i++)
#pragma unroll
                for (int j = 0; j < 4; j++)
                    FMA2(acc[i][j], am[i], bd[j], acc[i][j]);
        }
    }

#pragma unroll
    for (int i = 0; i < 4; i++) {
        int r0 = m0 + ty * 8 + 2 * i;
#pragma unroll
        for (int j = 0; j < 4; j++) {
            int col = n0 + tx * 4 + j;
            if (col < Nn) {
                float2 f = unpk(acc[i][j]);
                float bb = bias ? bias[col] : 0.f;
                Cm[(size_t)r0 * Nn + col] = f.x + bb;
                Cm[(size_t)(r0 + 1) * Nn + col] = f.y + bb;
            }
        }
    }
}

// ---------------------------------------------------------------------------
// Flash attention, GEMM-style with FFMA2 (reduction-axis pairing).
// Q tile 64, K tile 32. 256 threads. grid (N/64, H, B).
// ---------------------------------------------------------------------------
#define QT 64
#define KT 32

__global__ void __launch_bounds__(256) k_attn(const float* __restrict__ sf_ptr) {
    __shared__ float Qs[QT][HD];        // stride 68, 16B-aligned rows
    __shared__ float Ks[KT][HD];
    __shared__ float Vt[80][36];        // transposed V: [d][key], padded dims
    __shared__ float Ss[QT][36];        // scores / probs, stride 36 (16B-aligned)
    __shared__ float mrow[QT], lrow[QT], crow[QT], psc[KT];

    int b = blockIdx.z, h = blockIdx.y, q0 = blockIdx.x * QT;
    int tid = threadIdx.x;
    int tx = tid & 15, ty = tid >> 4;

    // stage Q
    for (int idx = tid; idx < QT * HD; idx += 256) {
        int r = idx / HD, d = idx - r * HD;
        Qs[r][d] = g_qkv[((size_t)(b * NN + q0 + r)) * QC + h * HD + d];
    }
    if (tid < QT) { mrow[tid] = -1e30f; lrow[tid] = 0.f; }

    ull acc[4][5];
#pragma unroll
    for (int i = 0; i < 4; i++)
#pragma unroll
        for (int d = 0; d < 5; d++) acc[i][d] = 0ull;

    const float sf = sf_ptr[0];
    const float scl = rsqrtf((float)HD);

    for (int kt = 0; kt < NN; kt += KT) {
        __syncthreads();   // protect Ks/Vt/Ss from previous iteration readers
        for (int idx = tid; idx < KT * HD; idx += 256) {
            int r = idx / HD, d = idx - r * HD;
            size_t off = ((size_t)(b * NN + kt + r)) * QC + h * HD + d;
            Ks[r][d] = g_qkv[off + CC];
            Vt[d][r] = g_qkv[off + 2 * CC];
        }
        if (tid < KT) {
            float pos = (float)(kt + tid) * (1.0f / (NN - 1));
            float dd = pos - 0.5f;
            psc[tid] = scl * __expf(-sf * dd * dd);
        }
        __syncthreads();

        // ---- S = Q K^T (f32x2, paired over k) ----
        ull s2[4][2];
#pragma unroll
        for (int i = 0; i < 4; i++) { s2[i][0] = 0ull; s2[i][1] = 0ull; }
#pragma unroll
        for (int k = 0; k < HD; k += 4) {
            ulonglong2 qv[4], kv[2];
#pragma unroll
            for (int i = 0; i < 4; i++)
                qv[i] = *(const ulonglong2*)&Qs[ty * 4 + i][k];
#pragma unroll
            for (int j = 0; j < 2; j++)
                kv[j] = *(const ulonglong2*)&Ks[tx * 2 + j][k];
#pragma unroll
            for (int i = 0; i < 4; i++)
#pragma unroll
                for (int j = 0; j < 2; j++) {
                    FMA2(s2[i][j], qv[i].x, kv[j].x, s2[i][j]);
                    FMA2(s2[i][j], qv[i].y, kv[j].y, s2[i][j]);
                }
        }
#pragma unroll
        for (int i = 0; i < 4; i++)
#pragma unroll
            for (int j = 0; j < 2; j++) {
                float2 f = unpk(s2[i][j]);
                Ss[ty * 4 + i][tx * 2 + j] = (f.x + f.y) * psc[tx * 2 + j];
            }
        __syncthreads();

        // ---- online softmax row update (4 threads per row) ----
        {
            int row = tid >> 2, part = tid & 3;
            float* sr = &Ss[row][part * 8];
            float tm = sr[0];
#pragma unroll
            for (int c = 1; c < 8; c++) tm = fmaxf(tm, sr[c]);
            tm = fmaxf(tm, __shfl_xor_sync(0xffffffffu, tm, 1));
            tm = fmaxf(tm, __shfl_xor_sync(0xffffffffu, tm, 2));
            float mold = mrow[row];
            float mnew = fmaxf(mold, tm);
            float ps = 0.f;
#pragma unroll
            for (int c = 0; c < 8; c++) {
                float e = __expf(sr[c] - mnew);
                sr[c] = e;
                ps += e;
            }
            ps += __shfl_xor_sync(0xffffffffu, ps, 1);
            ps += __shfl_xor_sync(0xffffffffu, ps, 2);
            if (part == 0) {
                float corr = __expf(mold - mnew);
                crow[row] = corr;
                lrow[row] = lrow[row] * corr + ps;
                mrow[row] = mnew;
            }
        }
        __syncthreads();

        // ---- rescale + O += P V (f32x2, paired over j) ----
#pragma unroll
        for (int i = 0; i < 4; i++) {
            ull c2; PACK2(c2, crow[ty * 4 + i]);
#pragma unroll
            for (int d = 0; d < 5; d++) MUL2(acc[i][d], acc[i][d], c2);
        }
#pragma unroll
        for (int j = 0; j < KT; j += 4) {
            ulonglong2 pv[4], vv[5];
#pragma unroll
            for (int i = 0; i < 4; i++)
                pv[i] = *(const ulonglong2*)&Ss[ty * 4 + i][j];
#pragma unroll
            for (int d = 0; d < 5; d++)
                vv[d] = *(const ulonglong2*)&Vt[tx * 5 + d][j];
#pragma unroll
            for (int i = 0; i < 4; i++)
#pragma unroll
                for (int d = 0; d < 5; d++) {
                    FMA2(acc[i][d], pv[i].x, vv[d].x, acc[i][d]);
                    FMA2(acc[i][d], pv[i].y, vv[d].y, acc[i][d]);
                }
        }
    }

    // epilogue: fold pairs, divide by l, store
#pragma unroll
    for (int i = 0; i < 4; i++) {
        int r = ty * 4 + i;
        float inv = 1.0f / lrow[r];
        float* op = g_ao + ((size_t)(b * NN + q0 + r)) * CC + h * HD;
#pragma unroll
        for (int dd = 0; dd < 5; dd++) {
            int d = tx * 5 + dd;
            if (d < HD) {
                float2 f = unpk(acc[i][dd]);
                op[d] = (f.x + f.y) * inv;
            }
        }
    }
}

// ---------------------------------------------------------------------------
extern "C" void kernel_launch(void* const* d_in, const int* in_sizes, int n_in,
                              void* d_out, int out_size) {
    const float* x       = (const float*)d_in[0];
    const float* norm_g  = (const float*)d_in[1];
    const float* norm_b  = (const float*)d_in[2];
    const float* ap_w    = (const float*)d_in[3];
    const float* ap_b    = (const float*)d_in[4];
    const float* norm2_g = (const float*)d_in[5];
    const float* norm2_b = (const float*)d_in[6];
    const float* qkv_w   = (const float*)d_in[7];
    const float* proj_w  = (const float*)d_in[8];
    const float* proj_b  = (const float*)d_in[9];
    const float* scaling = (const float*)d_in[10];
    float* out = (float*)d_out;

    float* xp  = (float*)0; (void)xp;

    k_ln_joint<<<Bb * NN, CC>>>(x, norm_g, norm_b, ap_w, ap_b);
    k_softmax_seq<<<Bb * JJ, 256>>>();
    k_pool_ln<<<Bb * NN, CC>>>(norm2_g, norm2_b);

    {   // QKV: A=g_xp [8192,544], B=qkv_w [1632,544]
        float* gxp; cudaGetSymbolAddress((void**)&gxp, g_xp);
        float* gq;  cudaGetSymbolAddress((void**)&gq,  g_qkv);
        k_sgemm<<<dim3((QC + BN - 1) / BN, (Bb * NN) / BM), 256>>>(gxp, qkv_w, gq, QC, CC, nullptr);
    }

    k_attn<<<dim3(NN / QT, HH, Bb), 256>>>(scaling);

    {   // proj: A=g_ao, B=proj_w [544,544]
        float* gao; cudaGetSymbolAddress((void**)&gao, g_ao);
        k_sgemm<<<dim3((CC + BN - 1) / BN, (Bb * NN) / BM), 256>>>(gao, proj_w, out, CC, CC, proj_b);
    }
}

// round 4
// speedup vs baseline: 1.4392x; 1.2425x over previous
#include <cuda_runtime.h>
#include <cuda_bf16.h>
#include <math.h>
#include <stdint.h>

typedef unsigned long long ull;

#define Bb 8
#define NN 1024
#define CC 544
#define JJ 17
#define FF 32
#define HH 8
#define HD 68
#define QC 1632

// packed f32x2 (attention)
#define FMA2(d,a,b,c) asm("fma.rn.f32x2 %0, %1, %2, %3;" : "=l"(d) : "l"(a), "l"(b), "l"(c))
#define MUL2(d,a,b)   asm("mul.rn.f32x2 %0, %1, %2;"     : "=l"(d) : "l"(a), "l"(b))
#define PACK2(d,x)    asm("mov.b64 %0, {%1, %1};"        : "=l"(d) : "f"(x))
__device__ __forceinline__ float2 unpk(ull v) {
    float2 r; asm("mov.b64 {%0, %1}, %2;" : "=f"(r.x), "=f"(r.y) : "l"(v)); return r;
}

// warp-level tensor core ops (family-common PTX; works on plain sm_103 target)
#define LDSM4(r0,r1,r2,r3,addr) \
    asm volatile("ldmatrix.sync.aligned.m8n8.x4.shared.b16 {%0,%1,%2,%3}, [%4];" \
        : "=r"(r0),"=r"(r1),"=r"(r2),"=r"(r3) : "r"(addr))
#define MMA16816(d,a,b) \
    asm volatile("mma.sync.aligned.m16n8k16.row.col.f32.bf16.bf16.f32 " \
        "{%0,%1,%2,%3}, {%4,%5,%6,%7}, {%8,%9}, {%0,%1,%2,%3};" \
        : "+f"((d)[0]),"+f"((d)[1]),"+f"((d)[2]),"+f"((d)[3]) \
        : "r"((a)[0]),"r"((a)[1]),"r"((a)[2]),"r"((a)[3]), "r"((b)[0]),"r"((b)[1]))

__device__ __forceinline__ uint32_t smem_u32(const void* p) {
    uint32_t a;
    asm("{ .reg .u64 t; cvta.to.shared.u64 t, %1; cvt.u32.u64 %0, t; }" : "=r"(a) : "l"(p));
    return a;
}

// -------- scratch --------
__device__ float g_xr [(size_t)Bb * NN * CC];
__device__ float g_sc [(size_t)Bb * NN * JJ];
__device__ float g_w  [(size_t)Bb * NN * JJ];
__device__ float g_qkv[(size_t)Bb * NN * QC];
// bf16 split operand buffers (A reused by pool_ln output and attention output)
__device__ __nv_bfloat16 g_ah [(size_t)Bb * NN * CC];
__device__ __nv_bfloat16 g_al [(size_t)Bb * NN * CC];
__device__ __nv_bfloat16 g_qbh[(size_t)QC * CC];
__device__ __nv_bfloat16 g_qbl[(size_t)QC * CC];
__device__ __nv_bfloat16 g_pbh[(size_t)CC * CC];
__device__ __nv_bfloat16 g_pbl[(size_t)CC * CC];

__device__ __forceinline__ float wsum(float v) {
#pragma unroll
    for (int o = 16; o > 0; o >>= 1) v += __shfl_xor_sync(0xffffffffu, v, o);
    return v;
}
__device__ __forceinline__ float wmax(float v) {
#pragma unroll
    for (int o = 16; o > 0; o >>= 1) v = fmaxf(v, __shfl_xor_sync(0xffffffffu, v, o));
    return v;
}

// ---------------------------------------------------------------------------
// Kernel 1: per-joint layernorm + pooling scores
// ---------------------------------------------------------------------------
__global__ void k_ln_joint(const float* __restrict__ x,
                           const float* __restrict__ ng,
                           const float* __restrict__ nb,
                           const float* __restrict__ apw,
                           const float* __restrict__ apb) {
    int bn = blockIdx.x;
    int j = threadIdx.x >> 5;
    int f = threadIdx.x & 31;

    float v = x[(size_t)bn * CC + j * FF + f];
    float mu = wsum(v) * (1.0f / FF);
    float d = v - mu;
    float var = wsum(d * d) * (1.0f / FF);
    float xn = d * rsqrtf(var + 1e-5f) * ng[f] + nb[f];
    g_xr[(size_t)bn * CC + j * FF + f] = xn;

    float sc = wsum(xn * apw[f]);
    if (f == 0) g_sc[(size_t)bn * JJ + j] = sc + apb[0];
}

// ---------------------------------------------------------------------------
// Kernel 2: softmax over sequence axis N per (b, joint)
// ---------------------------------------------------------------------------
__global__ void k_softmax_seq() {
    int bj = blockIdx.x;
    int b = bj / JJ, j = bj - b * JJ;
    int tid = threadIdx.x;
    const float* base = g_sc + (size_t)b * NN * JJ + j;

    float v[4];
#pragma unroll
    for (int i = 0; i < 4; i++) v[i] = base[(size_t)(tid + i * 256) * JJ];

    __shared__ float red[8];
    __shared__ float bc;
    int wid = tid >> 5, lane = tid & 31;

    float mx = fmaxf(fmaxf(v[0], v[1]), fmaxf(v[2], v[3]));
    mx = wmax(mx);
    if (lane == 0) red[wid] = mx;
    __syncthreads();
    if (tid == 0) {
        float m = red[0];
        for (int i = 1; i < 8; i++) m = fmaxf(m, red[i]);
        bc = m;
    }
    __syncthreads();
    mx = bc;
    __syncthreads();

    float se = 0.f;
#pragma unroll
    for (int i = 0; i < 4; i++) { v[i] = __expf(v[i] - mx); se += v[i]; }
    se = wsum(se);
    if (lane == 0) red[wid] = se;
    __syncthreads();
    if (tid == 0) {
        float s = 0.f;
        for (int i = 0; i < 8; i++) s += red[i];
        bc = 1.0f / s;
    }
    __syncthreads();
    float inv = bc;

    float* wbase = g_w + (size_t)b * NN * JJ + j;
#pragma unroll
    for (int i = 0; i < 4; i++) wbase[(size_t)(tid + i * 256) * JJ] = v[i] * inv;
}

// ---------------------------------------------------------------------------
// Kernel 3: pool + layernorm over C -> bf16 hi/lo operand
// ---------------------------------------------------------------------------
__global__ void k_pool_ln(const float* __restrict__ g2,
                          const float* __restrict__ b2) {
    int bn = blockIdx.x;
    int c = threadIdx.x;
    int wid = c >> 5, lane = c & 31;
    __shared__ float red[17];
    __shared__ float bc0, bc1;

    float v = g_xr[(size_t)bn * CC + c] * g_w[(size_t)bn * JJ + (c >> 5)];

    float s = wsum(v);
    if (lane == 0) red[wid] = s;
    __syncthreads();
    if (wid == 0) {
        float t = (lane < 17) ? red[lane] : 0.f;
        t = wsum(t);
        if (lane == 0) bc0 = t * (1.0f / CC);
    }
    __syncthreads();
    float mu = bc0;
    float d = v - mu;

    float s2 = wsum(d * d);
    if (lane == 0) red[wid] = s2;
    __syncthreads();
    if (wid == 0) {
        float t = (lane < 17) ? red[lane] : 0.f;
        t = wsum(t);
        if (lane == 0) bc1 = t * (1.0f / CC);
    }
    __syncthreads();
    float var = bc1;

    float xp = d * rsqrtf(var + 1e-5f) * g2[c] + b2[c];
    __nv_bfloat16 h = __float2bfloat16(xp);
    __nv_bfloat16 l = __float2bfloat16(xp - __bfloat162float(h));
    size_t o = (size_t)bn * CC + c;
    g_ah[o] = h; g_al[o] = l;
}

// ---------------------------------------------------------------------------
// Weight conversion: fp32 [rows,cols] -> bf16 hi/lo
// ---------------------------------------------------------------------------
__global__ void k_cvt_w(const float* __restrict__ W,
                        __nv_bfloat16* __restrict__ bh,
                        __nv_bfloat16* __restrict__ bl,
                        int total) {
    int idx = blockIdx.x * 256 + threadIdx.x;
    if (idx >= total) return;
    float v = W[idx];
    __nv_bfloat16 h = __float2bfloat16(v);
    bh[idx] = h;
    bl[idx] = __float2bfloat16(v - __bfloat162float(h));
}

// ---------------------------------------------------------------------------
// mma.sync bf16 split GEMM: C[M,Nn] = A[M,K] @ B[Nn,K]^T (+bias)
// BM=128, BN=128, BK=32, 256 threads = 8 warps (4m x 2n), warp tile 32x64.
// K = 544 = 17 chunks of 32. 3 passes (hh, hl, lh) for fp32-like precision.
// ---------------------------------------------------------------------------
#define GBM 128
#define GBN 128
#define GBK 32
#define SST 40   // smem row stride in halves (80B, conflict-free ldmatrix)

__global__ void __launch_bounds__(256) k_mma_gemm(
        const __nv_bfloat16* __restrict__ Ah, const __nv_bfloat16* __restrict__ Al,
        const __nv_bfloat16* __restrict__ Bh, const __nv_bfloat16* __restrict__ Bl,
        float* __restrict__ Cm, int Nn, const float* __restrict__ bias) {
    __shared__ __nv_bfloat16 sAh[GBM * SST], sAl[GBM * SST];
    __shared__ __nv_bfloat16 sBh[GBN * SST], sBl[GBN * SST];

    int tid = threadIdx.x;
    int lane = tid & 31, warp = tid >> 5;
    int wm = warp >> 1, wn = warp & 1;          // 4 x 2 warp grid
    int m0 = blockIdx.y * GBM, n0 = blockIdx.x * GBN;

    uint32_t bAh = smem_u32(sAh), bAl = smem_u32(sAl);
    uint32_t bBh = smem_u32(sBh), bBl = smem_u32(sBl);

    float acc[2][8][4];
#pragma unroll
    for (int i = 0; i < 2; i++)
#pragma unroll
        for (int j = 0; j < 8; j++)
#pragma unroll
            for (int r = 0; r < 4; r++) acc[i][j][r] = 0.f;

    // ldmatrix source addresses (per-warp, constant across chunks)
    // A: row = wm*32 + mf*16 + (lane&15), koff = 8*(lane>>4)
    // B: row = wn*64 + nfp*16 + (lane&7) + 8*(lane>>4), koff = 8*((lane>>3)&1)
    uint32_t aoff[2];
#pragma unroll
    for (int mf = 0; mf < 2; mf++)
        aoff[mf] = (uint32_t)(((wm * 32 + mf * 16 + (lane & 15)) * SST + 8 * (lane >> 4)) * 2);
    uint32_t boff[4];
#pragma unroll
    for (int nfp = 0; nfp < 4; nfp++)
        boff[nfp] = (uint32_t)(((wn * 64 + nfp * 16 + (lane & 7) + 8 * (lane >> 4)) * SST
                                + 8 * ((lane >> 3) & 1)) * 2);

    int lrow = tid >> 2;          // 0..63 (x2 halves of matrix rows)
    int lc = (tid & 3) * 8;       // half-offset within 32-half row chunk

    for (int ck = 0; ck < 17; ck++) {
        int kb = ck * GBK;
        // load A hi/lo rows [m0..m0+127], B hi/lo rows [n0..n0+127] (guarded)
#pragma unroll
        for (int half = 0; half < 2; half++) {
            int row = lrow + half * 64;
            const __nv_bfloat16* pa_h = Ah + (size_t)(m0 + row) * CC + kb + lc;
            const __nv_bfloat16* pa_l = Al + (size_t)(m0 + row) * CC + kb + lc;
            uint4 vh = *(const uint4*)pa_h;
            uint4 vl = *(const uint4*)pa_l;
            *(uint4*)(sAh + row * SST + lc) = vh;
            *(uint4*)(sAl + row * SST + lc) = vl;
            uint4 wh = make_uint4(0, 0, 0, 0), wl = make_uint4(0, 0, 0, 0);
            if (n0 + row < Nn) {
                wh = *(const uint4*)(Bh + (size_t)(n0 + row) * CC + kb + lc);
                wl = *(const uint4*)(Bl + (size_t)(n0 + row) * CC + kb + lc);
            }
            *(uint4*)(sBh + row * SST + lc) = wh;
            *(uint4*)(sBl + row * SST + lc) = wl;
        }
        __syncthreads();

#pragma unroll
        for (int ks = 0; ks < 2; ks++) {
            uint32_t kadd = (uint32_t)(ks * 16 * 2);
            uint32_t ah[2][4], al[2][4];
#pragma unroll
            for (int mf = 0; mf < 2; mf++) {
                LDSM4(ah[mf][0], ah[mf][1], ah[mf][2], ah[mf][3], bAh + aoff[mf] + kadd);
                LDSM4(al[mf][0], al[mf][1], al[mf][2], al[mf][3], bAl + aoff[mf] + kadd);
            }
#pragma unroll
            for (int nfp = 0; nfp < 4; nfp++) {
                uint32_t bh4[4], bl4[4];
                LDSM4(bh4[0], bh4[1], bh4[2], bh4[3], bBh + boff[nfp] + kadd);
                LDSM4(bl4[0], bl4[1], bl4[2], bl4[3], bBl + boff[nfp] + kadd);
#pragma unroll
                for (int mf = 0; mf < 2; mf++)
#pragma unroll
                    for (int sub = 0; sub < 2; sub++) {
                        int nf = nfp * 2 + sub;
                        MMA16816(acc[mf][nf], ah[mf], bh4 + 2 * sub);   // hh
                        MMA16816(acc[mf][nf], ah[mf], bl4 + 2 * sub);   // hl
                        MMA16816(acc[mf][nf], al[mf], bh4 + 2 * sub);   // lh
                    }
            }
        }
        __syncthreads();
    }

    // epilogue
#pragma unroll
    for (int mf = 0; mf < 2; mf++) {
        int r0 = m0 + wm * 32 + mf * 16 + (lane >> 2);
#pragma unroll
        for (int nf = 0; nf < 8; nf++) {
            int col = n0 + wn * 64 + nf * 8 + 2 * (lane & 3);
            if (col < Nn) {
                float b0 = bias ? bias[col] : 0.f;
                float b1 = bias ? bias[col + 1] : 0.f;
                *(float2*)(Cm + (size_t)r0 * Nn + col) =
                    make_float2(acc[mf][nf][0] + b0, acc[mf][nf][1] + b1);
                *(float2*)(Cm + (size_t)(r0 + 8) * Nn + col) =
                    make_float2(acc[mf][nf][2] + b0, acc[mf][nf][3] + b1);
            }
        }
    }
}

// ---------------------------------------------------------------------------
// Flash attention (FFMA2), emits bf16 hi/lo operand for proj GEMM.
// ---------------------------------------------------------------------------
#define QT 64
#define KT 32

__global__ void __launch_bounds__(256) k_attn(const float* __restrict__ sf_ptr) {
    __shared__ float Qs[QT][HD];
    __shared__ float Ks[KT][HD];
    __shared__ float Vt[80][36];
    __shared__ float Ss[QT][36];
    __shared__ float mrow[QT], lrow_[QT], crow[QT], psc[KT];

    int b = blockIdx.z, h = blockIdx.y, q0 = blockIdx.x * QT;
    int tid = threadIdx.x;
    int tx = tid & 15, ty = tid >> 4;

    for (int idx = tid; idx < QT * HD; idx += 256) {
        int r = idx / HD, d = idx - r * HD;
        Qs[r][d] = g_qkv[((size_t)(b * NN + q0 + r)) * QC + h * HD + d];
    }
    if (tid < QT) { mrow[tid] = -1e30f; lrow_[tid] = 0.f; }

    ull acc[4][5];
#pragma unroll
    for (int i = 0; i < 4; i++)
#pragma unroll
        for (int d = 0; d < 5; d++) acc[i][d] = 0ull;

    const float sf = sf_ptr[0];
    const float scl = rsqrtf((float)HD);

    for (int kt = 0; kt < NN; kt += KT) {
        __syncthreads();
        for (int idx = tid; idx < KT * HD; idx += 256) {
            int r = idx / HD, d = idx - r * HD;
            size_t off = ((size_t)(b * NN + kt + r)) * QC + h * HD + d;
            Ks[r][d] = g_qkv[off + CC];
            Vt[d][r] = g_qkv[off + 2 * CC];
        }
        if (tid < KT) {
            float pos = (float)(kt + tid) * (1.0f / (NN - 1));
            float dd = pos - 0.5f;
            psc[tid] = scl * __expf(-sf * dd * dd);
        }
        __syncthreads();

        ull s2[4][2];
#pragma unroll
        for (int i = 0; i < 4; i++) { s2[i][0] = 0ull; s2[i][1] = 0ull; }
#pragma unroll
        for (int k = 0; k < HD; k += 4) {
            ulonglong2 qv[4], kv[2];
#pragma unroll
            for (int i = 0; i < 4; i++)
                qv[i] = *(const ulonglong2*)&Qs[ty * 4 + i][k];
#pragma unroll
            for (int j = 0; j < 2; j++)
                kv[j] = *(const ulonglong2*)&Ks[tx * 2 + j][k];
#pragma unroll
            for (int i = 0; i < 4; i++)
#pragma unroll
                for (int j = 0; j < 2; j++) {
                    FMA2(s2[i][j], qv[i].x, kv[j].x, s2[i][j]);
                    FMA2(s2[i][j], qv[i].y, kv[j].y, s2[i][j]);
                }
        }
#pragma unroll
        for (int i = 0; i < 4; i++)
#pragma unroll
            for (int j = 0; j < 2; j++) {
                float2 f = unpk(s2[i][j]);
                Ss[ty * 4 + i][tx * 2 + j] = (f.x + f.y) * psc[tx * 2 + j];
            }
        __syncthreads();

        {
            int row = tid >> 2, part = tid & 3;
            float* sr = &Ss[row][part * 8];
            float tm = sr[0];
#pragma unroll
            for (int c = 1; c < 8; c++) tm = fmaxf(tm, sr[c]);
            tm = fmaxf(tm, __shfl_xor_sync(0xffffffffu, tm, 1));
            tm = fmaxf(tm, __shfl_xor_sync(0xffffffffu, tm, 2));
            float mold = mrow[row];
            float mnew = fmaxf(mold, tm);
            float ps = 0.f;
#pragma unroll
            for (int c = 0; c < 8; c++) {
                float e = __expf(sr[c] - mnew);
                sr[c] = e;
                ps += e;
            }
            ps += __shfl_xor_sync(0xffffffffu, ps, 1);
            ps += __shfl_xor_sync(0xffffffffu, ps, 2);
            if (part == 0) {
                float corr = __expf(mold - mnew);
                crow[row] = corr;
                lrow_[row] = lrow_[row] * corr + ps;
                mrow[row] = mnew;
            }
        }
        __syncthreads();

#pragma unroll
        for (int i = 0; i < 4; i++) {
            ull c2; PACK2(c2, crow[ty * 4 + i]);
#pragma unroll
            for (int d = 0; d < 5; d++) MUL2(acc[i][d], acc[i][d], c2);
        }
#pragma unroll
        for (int j = 0; j < KT; j += 4) {
            ulonglong2 pv[4], vv[5];
#pragma unroll
            for (int i = 0; i < 4; i++)
                pv[i] = *(const ulonglong2*)&Ss[ty * 4 + i][j];
#pragma unroll
            for (int d = 0; d < 5; d++)
                vv[d] = *(const ulonglong2*)&Vt[tx * 5 + d][j];
#pragma unroll
            for (int i = 0; i < 4; i++)
#pragma unroll
                for (int d = 0; d < 5; d++) {
                    FMA2(acc[i][d], pv[i].x, vv[d].x, acc[i][d]);
                    FMA2(acc[i][d], pv[i].y, vv[d].y, acc[i][d]);
                }
        }
    }

    // epilogue: fold, normalize, emit bf16 hi/lo for proj GEMM
#pragma unroll
    for (int i = 0; i < 4; i++) {
        int r = ty * 4 + i;
        float inv = 1.0f / lrow_[r];
        size_t rowo = ((size_t)(b * NN + q0 + r)) * CC + h * HD;
#pragma unroll
        for (int dd = 0; dd < 5; dd++) {
            int d = tx * 5 + dd;
            if (d < HD) {
                float2 f = unpk(acc[i][dd]);
                float o = (f.x + f.y) * inv;
                __nv_bfloat16 hh = __float2bfloat16(o);
                g_ah[rowo + d] = hh;
                g_al[rowo + d] = __float2bfloat16(o - __bfloat162float(hh));
            }
        }
    }
}

// ---------------------------------------------------------------------------
extern "C" void kernel_launch(void* const* d_in, const int* in_sizes, int n_in,
                              void* d_out, int out_size) {
    const float* x       = (const float*)d_in[0];
    const float* norm_g  = (const float*)d_in[1];
    const float* norm_b  = (const float*)d_in[2];
    const float* ap_w    = (const float*)d_in[3];
    const float* ap_b    = (const float*)d_in[4];
    const float* norm2_g = (const float*)d_in[5];
    const float* norm2_b = (const float*)d_in[6];
    const float* qkv_w   = (const float*)d_in[7];
    const float* proj_w  = (const float*)d_in[8];
    const float* proj_b  = (const float*)d_in[9];
    const float* scaling = (const float*)d_in[10];
    float* out = (float*)d_out;

    float *gq;
    __nv_bfloat16 *p_qbh, *p_qbl, *p_pbh, *p_pbl, *p_ah, *p_al;
    cudaGetSymbolAddress((void**)&gq, g_qkv);
    cudaGetSymbolAddress((void**)&p_qbh, g_qbh);
    cudaGetSymbolAddress((void**)&p_qbl, g_qbl);
    cudaGetSymbolAddress((void**)&p_pbh, g_pbh);
    cudaGetSymbolAddress((void**)&p_pbl, g_pbl);
    cudaGetSymbolAddress((void**)&p_ah, g_ah);
    cudaGetSymbolAddress((void**)&p_al, g_al);

    k_ln_joint<<<Bb * NN, CC>>>(x, norm_g, norm_b, ap_w, ap_b);
    k_softmax_seq<<<Bb * JJ, 256>>>();
    k_pool_ln<<<Bb * NN, CC>>>(norm2_g, norm2_b);

    k_cvt_w<<<(QC * CC + 255) / 256, 256>>>(qkv_w, p_qbh, p_qbl, QC * CC);
    k_mma_gemm<<<dim3(13, (Bb * NN) / GBM), 256>>>(p_ah, p_al, p_qbh, p_qbl,
                                                   gq, QC, nullptr);

    k_attn<<<dim3(NN / QT, HH, Bb), 256>>>(scaling);

    k_cvt_w<<<(CC * CC + 255) / 256, 256>>>(proj_w, p_pbh, p_pbl, CC * CC);
    k_mma_gemm<<<dim3(5, (Bb * NN) / GBM), 256>>>(p_ah, p_al, p_pbh, p_pbl,
                                                  out, CC, proj_b);
}

// round 5
// speedup vs baseline: 2.2843x; 1.5872x over previous
#include <cuda_runtime.h>
#include <cuda_bf16.h>
#include <math.h>
#include <stdint.h>

typedef unsigned long long ull;

#define Bb 8
#define NN 1024
#define CC 544
#define JJ 17
#define FF 32
#define HH 8
#define HD 68
#define QC 1632
#define DP 80     // padded head dim

// tensor-core warp ops (family-common PTX, OK on plain sm_103 target)
#define LDSM4(r0,r1,r2,r3,addr) \
    asm volatile("ldmatrix.sync.aligned.m8n8.x4.shared.b16 {%0,%1,%2,%3}, [%4];" \
        : "=r"(r0),"=r"(r1),"=r"(r2),"=r"(r3) : "r"(addr))
#define MMA16816(d,a,b) \
    asm volatile("mma.sync.aligned.m16n8k16.row.col.f32.bf16.bf16.f32 " \
        "{%0,%1,%2,%3}, {%4,%5,%6,%7}, {%8,%9}, {%0,%1,%2,%3};" \
        : "+f"((d)[0]),"+f"((d)[1]),"+f"((d)[2]),"+f"((d)[3]) \
        : "r"((a)[0]),"r"((a)[1]),"r"((a)[2]),"r"((a)[3]), "r"((b)[0]),"r"((b)[1]))
// pack two f32 -> bf16x2 (first src = high half)
#define CVT2(d, lo, hi) asm("cvt.rn.bf16x2.f32 %0, %1, %2;" : "=r"(d) : "f"(hi), "f"(lo))

__device__ __forceinline__ uint32_t smem_u32(const void* p) {
    uint32_t a;
    asm("{ .reg .u64 t; cvta.to.shared.u64 t, %1; cvt.u32.u64 %0, t; }" : "=r"(a) : "l"(p));
    return a;
}
__device__ __forceinline__ void packsplit(uint32_t* hp, uint32_t* lp, float v0, float v1) {
    uint32_t h; CVT2(h, v0, v1);
    float l0 = v0 - __uint_as_float(h << 16);
    float l1 = v1 - __uint_as_float(h & 0xffff0000u);
    uint32_t l; CVT2(l, l0, l1);
    *hp = h; *lp = l;
}

// -------- scratch --------
__device__ float g_xr [(size_t)Bb * NN * CC];
__device__ float g_sc [(size_t)Bb * NN * JJ];
__device__ float g_w  [(size_t)Bb * NN * JJ];
__device__ __nv_bfloat16 g_ah [(size_t)Bb * NN * CC];   // GEMM A hi (xp, then attn-out)
__device__ __nv_bfloat16 g_al [(size_t)Bb * NN * CC];
__device__ __nv_bfloat16 g_qbh[(size_t)QC * CC];
__device__ __nv_bfloat16 g_qbl[(size_t)QC * CC];
__device__ __nv_bfloat16 g_pbh[(size_t)CC * CC];
__device__ __nv_bfloat16 g_pbl[(size_t)CC * CC];
// attention operands, [bh][n][DP]
__device__ __nv_bfloat16 g_qh [(size_t)Bb * HH * NN * DP];
__device__ __nv_bfloat16 g_ql [(size_t)Bb * HH * NN * DP];
__device__ __nv_bfloat16 g_kh [(size_t)Bb * HH * NN * DP];
__device__ __nv_bfloat16 g_kl [(size_t)Bb * HH * NN * DP];
__device__ __nv_bfloat16 g_vh [(size_t)Bb * HH * NN * DP];
__device__ __nv_bfloat16 g_vl [(size_t)Bb * HH * NN * DP];
// V transposed, [bh][d=DP][n]
__device__ __nv_bfloat16 g_vth[(size_t)Bb * HH * DP * NN];
__device__ __nv_bfloat16 g_vtl[(size_t)Bb * HH * DP * NN];

__device__ __forceinline__ float wsum(float v) {
#pragma unroll
    for (int o = 16; o > 0; o >>= 1) v += __shfl_xor_sync(0xffffffffu, v, o);
    return v;
}
__device__ __forceinline__ float wmax(float v) {
#pragma unroll
    for (int o = 16; o > 0; o >>= 1) v = fmaxf(v, __shfl_xor_sync(0xffffffffu, v, o));
    return v;
}

// ---------------------------------------------------------------------------
// Kernel 1: per-joint layernorm + pooling scores
// ---------------------------------------------------------------------------
__global__ void k_ln_joint(const float* __restrict__ x,
                           const float* __restrict__ ng,
                           const float* __restrict__ nb,
                           const float* __restrict__ apw,
                           const float* __restrict__ apb) {
    int bn = blockIdx.x;
    int j = threadIdx.x >> 5;
    int f = threadIdx.x & 31;

    float v = x[(size_t)bn * CC + j * FF + f];
    float mu = wsum(v) * (1.0f / FF);
    float d = v - mu;
    float var = wsum(d * d) * (1.0f / FF);
    float xn = d * rsqrtf(var + 1e-5f) * ng[f] + nb[f];
    g_xr[(size_t)bn * CC + j * FF + f] = xn;

    float sc = wsum(xn * apw[f]);
    if (f == 0) g_sc[(size_t)bn * JJ + j] = sc + apb[0];
}

// ---------------------------------------------------------------------------
// Kernel 2: softmax over sequence axis N per (b, joint)
// ---------------------------------------------------------------------------
__global__ void k_softmax_seq() {
    int bj = blockIdx.x;
    int b = bj / JJ, j = bj - b * JJ;
    int tid = threadIdx.x;
    const float* base = g_sc + (size_t)b * NN * JJ + j;

    float v[4];
#pragma unroll
    for (int i = 0; i < 4; i++) v[i] = base[(size_t)(tid + i * 256) * JJ];

    __shared__ float red[8];
    __shared__ float bc;
    int wid = tid >> 5, lane = tid & 31;

    float mx = fmaxf(fmaxf(v[0], v[1]), fmaxf(v[2], v[3]));
    mx = wmax(mx);
    if (lane == 0) red[wid] = mx;
    __syncthreads();
    if (tid == 0) {
        float m = red[0];
        for (int i = 1; i < 8; i++) m = fmaxf(m, red[i]);
        bc = m;
    }
    __syncthreads();
    mx = bc;
    __syncthreads();

    float se = 0.f;
#pragma unroll
    for (int i = 0; i < 4; i++) { v[i] = __expf(v[i] - mx); se += v[i]; }
    se = wsum(se);
    if (lane == 0) red[wid] = se;
    __syncthreads();
    if (tid == 0) {
        float s = 0.f;
        for (int i = 0; i < 8; i++) s += red[i];
        bc = 1.0f / s;
    }
    __syncthreads();
    float inv = bc;

    float* wbase = g_w + (size_t)b * NN * JJ + j;
#pragma unroll
    for (int i = 0; i < 4; i++) wbase[(size_t)(tid + i * 256) * JJ] = v[i] * inv;
}

// ---------------------------------------------------------------------------
// Kernel 3: pool + layernorm over C -> bf16 hi/lo operand
// ---------------------------------------------------------------------------
__global__ void k_pool_ln(const float* __restrict__ g2,
                          const float* __restrict__ b2) {
    int bn = blockIdx.x;
    int c = threadIdx.x;
    int wid = c >> 5, lane = c & 31;
    __shared__ float red[17];
    __shared__ float bc0, bc1;

    float v = g_xr[(size_t)bn * CC + c] * g_w[(size_t)bn * JJ + (c >> 5)];

    float s = wsum(v);
    if (lane == 0) red[wid] = s;
    __syncthreads();
    if (wid == 0) {
        float t = (lane < 17) ? red[lane] : 0.f;
        t = wsum(t);
        if (lane == 0) bc0 = t * (1.0f / CC);
    }
    __syncthreads();
    float mu = bc0;
    float d = v - mu;

    float s2 = wsum(d * d);
    if (lane == 0) red[wid] = s2;
    __syncthreads();
    if (wid == 0) {
        float t = (lane < 17) ? red[lane] : 0.f;
        t = wsum(t);
        if (lane == 0) bc1 = t * (1.0f / CC);
    }
    __syncthreads();
    float var = bc1;

    float xp = d * rsqrtf(var + 1e-5f) * g2[c] + b2[c];
    __nv_bfloat16 h = __float2bfloat16(xp);
    __nv_bfloat16 l = __float2bfloat16(xp - __bfloat162float(h));
    size_t o = (size_t)bn * CC + c;
    g_ah[o] = h; g_al[o] = l;
}

// ---------------------------------------------------------------------------
// Weight conversion fp32 -> bf16 hi/lo
// ---------------------------------------------------------------------------
__global__ void k_cvt_w(const float* __restrict__ W,
                        __nv_bfloat16* __restrict__ bh,
                        __nv_bfloat16* __restrict__ bl,
                        int total) {
    int idx = blockIdx.x * 256 + threadIdx.x;
    if (idx >= total) return;
    float v = W[idx];
    __nv_bfloat16 h = __float2bfloat16(v);
    bh[idx] = h;
    bl[idx] = __float2bfloat16(v - __bfloat162float(h));
}

// ---------------------------------------------------------------------------
// Zero the d-pad region (68..79) of Q/K/V operand buffers
// ---------------------------------------------------------------------------
__global__ void k_zero_pad() {
    int idx = blockIdx.x * 256 + threadIdx.x;
    if (idx >= 64 * 1024 * (DP - HD)) return;
    int bhn = idx / (DP - HD), d = HD + (idx - bhn * (DP - HD));
    size_t ad = (size_t)bhn * DP + d;
    __nv_bfloat16 z = __float2bfloat16(0.f);
    g_qh[ad] = z; g_ql[ad] = z;
    g_kh[ad] = z; g_kl[ad] = z;
    g_vh[ad] = z; g_vl[ad] = z;
}

// ---------------------------------------------------------------------------
// V transpose: [bh][n][DP] -> [bh][d][n]
// ---------------------------------------------------------------------------
__global__ void k_vt() {
    __shared__ __nv_bfloat16 t0[32][33], t1[32][33];
    int n0 = blockIdx.x * 32, d0 = blockIdx.y * 32, bh = blockIdx.z;
    int tx = threadIdx.x, ty = threadIdx.y;
    int d = d0 + tx;
#pragma unroll
    for (int i = 0; i < 4; i++) {
        int n = n0 + ty + i * 8;
        if (d < DP) {
            t0[ty + i * 8][tx] = g_vh[((size_t)bh * NN + n) * DP + d];
            t1[ty + i * 8][tx] = g_vl[((size_t)bh * NN + n) * DP + d];
        }
    }
    __syncthreads();
#pragma unroll
    for (int i = 0; i < 4; i++) {
        int dd = d0 + ty + i * 8;
        if (dd < DP) {
            g_vth[((size_t)bh * DP + dd) * NN + n0 + tx] = t0[tx][ty + i * 8];
            g_vtl[((size_t)bh * DP + dd) * NN + n0 + tx] = t1[tx][ty + i * 8];
        }
    }
}

// ---------------------------------------------------------------------------
// mma.sync bf16 split GEMM. mode 0: store fp32 C (+bias). mode 1: scatter QKV.
// ---------------------------------------------------------------------------
#define GBM 128
#define GBN 128
#define GBK 32
#define SST 40

__global__ void __launch_bounds__(256) k_mma_gemm(
        const __nv_bfloat16* __restrict__ Ah, const __nv_bfloat16* __restrict__ Al,
        const __nv_bfloat16* __restrict__ Bh, const __nv_bfloat16* __restrict__ Bl,
        float* __restrict__ Cm, int Nn, const float* __restrict__ bias, int mode) {
    __shared__ __nv_bfloat16 sAh[GBM * SST], sAl[GBM * SST];
    __shared__ __nv_bfloat16 sBh[GBN * SST], sBl[GBN * SST];

    int tid = threadIdx.x;
    int lane = tid & 31, warp = tid >> 5;
    int wm = warp >> 1, wn = warp & 1;
    int m0 = blockIdx.y * GBM, n0 = blockIdx.x * GBN;

    uint32_t bAh = smem_u32(sAh), bAl = smem_u32(sAl);
    uint32_t bBh = smem_u32(sBh), bBl = smem_u32(sBl);

    float acc[2][8][4];
#pragma unroll
    for (int i = 0; i < 2; i++)
#pragma unroll
        for (int j = 0; j < 8; j++)
#pragma unroll
            for (int r = 0; r < 4; r++) acc[i][j][r] = 0.f;

    uint32_t aoff[2];
#pragma unroll
    for (int mf = 0; mf < 2; mf++)
        aoff[mf] = (uint32_t)(((wm * 32 + mf * 16 + (lane & 15)) * SST + 8 * (lane >> 4)) * 2);
    uint32_t boff[4];
#pragma unroll
    for (int nfp = 0; nfp < 4; nfp++)
        boff[nfp] = (uint32_t)(((wn * 64 + nfp * 16 + (lane & 7) + 8 * (lane >> 4)) * SST
                                + 8 * ((lane >> 3) & 1)) * 2);

    int lrow = tid >> 2;
    int lc = (tid & 3) * 8;

    for (int ck = 0; ck < 17; ck++) {
        int kb = ck * GBK;
#pragma unroll
        for (int half = 0; half < 2; half++) {
            int row = lrow + half * 64;
            uint4 vh = *(const uint4*)(Ah + (size_t)(m0 + row) * CC + kb + lc);
            uint4 vl = *(const uint4*)(Al + (size_t)(m0 + row) * CC + kb + lc);
            *(uint4*)(sAh + row * SST + lc) = vh;
            *(uint4*)(sAl + row * SST + lc) = vl;
            uint4 wh = make_uint4(0, 0, 0, 0), wl = make_uint4(0, 0, 0, 0);
            if (n0 + row < Nn) {
                wh = *(const uint4*)(Bh + (size_t)(n0 + row) * CC + kb + lc);
                wl = *(const uint4*)(Bl + (size_t)(n0 + row) * CC + kb + lc);
            }
            *(uint4*)(sBh + row * SST + lc) = wh;
            *(uint4*)(sBl + row * SST + lc) = wl;
        }
        __syncthreads();

#pragma unroll
        for (int ks = 0; ks < 2; ks++) {
            uint32_t kadd = (uint32_t)(ks * 16 * 2);
            uint32_t ah[2][4], al[2][4];
#pragma unroll
            for (int mf = 0; mf < 2; mf++) {
                LDSM4(ah[mf][0], ah[mf][1], ah[mf][2], ah[mf][3], bAh + aoff[mf] + kadd);
                LDSM4(al[mf][0], al[mf][1], al[mf][2], al[mf][3], bAl + aoff[mf] + kadd);
            }
#pragma unroll
            for (int nfp = 0; nfp < 4; nfp++) {
                uint32_t bh4[4], bl4[4];
                LDSM4(bh4[0], bh4[1], bh4[2], bh4[3], bBh + boff[nfp] + kadd);
                LDSM4(bl4[0], bl4[1], bl4[2], bl4[3], bBl + boff[nfp] + kadd);
#pragma unroll
                for (int mf = 0; mf < 2; mf++)
#pragma unroll
                    for (int sub = 0; sub < 2; sub++) {
                        int nf = nfp * 2 + sub;
                        MMA16816(acc[mf][nf], ah[mf], bh4 + 2 * sub);
                        MMA16816(acc[mf][nf], ah[mf], bl4 + 2 * sub);
                        MMA16816(acc[mf][nf], al[mf], bh4 + 2 * sub);
                    }
            }
        }
        __syncthreads();
    }

    if (mode == 0) {
#pragma unroll
        for (int mf = 0; mf < 2; mf++) {
            int r0 = m0 + wm * 32 + mf * 16 + (lane >> 2);
#pragma unroll
            for (int nf = 0; nf < 8; nf++) {
                int col = n0 + wn * 64 + nf * 8 + 2 * (lane & 3);
                if (col < Nn) {
                    float b0 = bias ? bias[col] : 0.f;
                    float b1 = bias ? bias[col + 1] : 0.f;
                    *(float2*)(Cm + (size_t)r0 * Nn + col) =
                        make_float2(acc[mf][nf][0] + b0, acc[mf][nf][1] + b1);
                    *(float2*)(Cm + (size_t)(r0 + 8) * Nn + col) =
                        make_float2(acc[mf][nf][2] + b0, acc[mf][nf][3] + b1);
                }
            }
        }
    } else {
        // scatter to Q/K/V bf16 hi/lo, layout [bh][n][DP]
#pragma unroll
        for (int mf = 0; mf < 2; mf++) {
            int r0 = m0 + wm * 32 + mf * 16 + (lane >> 2);
#pragma unroll
            for (int nf = 0; nf < 8; nf++) {
                int col = n0 + wn * 64 + nf * 8 + 2 * (lane & 3);
                if (col < QC) {
                    int s = (col >= 1088) ? 2 : (col >= 544 ? 1 : 0);
                    int rem = col - s * 544;
                    int hh = rem / 68;
                    int d = rem - hh * 68;     // even, d+1 <= 67
                    __nv_bfloat16* Dh = (s == 0) ? g_qh : (s == 1) ? g_kh : g_vh;
                    __nv_bfloat16* Dl = (s == 0) ? g_ql : (s == 1) ? g_kl : g_vl;
#pragma unroll
                    for (int rr = 0; rr < 2; rr++) {
                        int row = r0 + rr * 8;
                        int bb = row >> 10, nn = row & 1023;
                        size_t ad = ((size_t)(bb * HH + hh) * NN + nn) * DP + d;
                        uint32_t hp, lp;
                        packsplit(&hp, &lp, acc[mf][nf][rr * 2], acc[mf][nf][rr * 2 + 1]);
                        *(uint32_t*)(Dh + ad) = hp;
                        *(uint32_t*)(Dl + ad) = lp;
                    }
                }
            }
        }
    }
}

// ---------------------------------------------------------------------------
// Flash attention with mma.sync, bf16 split QK^T and PV.
// Block = (b, h, 128 queries), 8 warps x m16. 64-key tiles.
// ---------------------------------------------------------------------------
#define AQT 128
#define AKT 64
#define KSTR 88
#define VSTR 72

__global__ void __launch_bounds__(256) k_attn_mma(const float* __restrict__ sf_ptr) {
    __shared__ __nv_bfloat16 sK[2][AKT * KSTR];   // hi, lo (also Q staging)
    __shared__ __nv_bfloat16 sV[2][DP * VSTR];
    __shared__ float psc[AKT];

    int tid = threadIdx.x, lane = tid & 31, warp = tid >> 5;
    int b = blockIdx.z, h = blockIdx.y, q0 = blockIdx.x * AQT;
    int bh = b * HH + h;
    uint32_t bK0 = smem_u32(sK[0]), bK1 = smem_u32(sK[1]);
    uint32_t bV0 = smem_u32(sV[0]), bV1 = smem_u32(sV[1]);

    const float sf = sf_ptr[0];
    const float scl = rsqrtf((float)HD);

    uint32_t aoff = (uint32_t)(((warp * 16 + (lane & 15)) * KSTR + 8 * (lane >> 4)) * 2);
    uint32_t boffS[4], voffB[5];
#pragma unroll
    for (int nfp = 0; nfp < 4; nfp++)
        boffS[nfp] = (uint32_t)(((nfp * 16 + (lane & 7) + 8 * (lane >> 4)) * KSTR
                                 + 8 * ((lane >> 3) & 1)) * 2);
#pragma unroll
    for (int nfp = 0; nfp < 5; nfp++)
        voffB[nfp] = (uint32_t)(((nfp * 16 + (lane & 7) + 8 * (lane >> 4)) * VSTR
                                 + 8 * ((lane >> 3) & 1)) * 2);

    // ---- stage Q hi then lo, extract A-frags ----
    uint32_t qh[5][4], ql[5][4];
    __nv_bfloat16* sQ = &sK[0][0];    // 128 x KSTR region spans sK[0..1]
    {
        const __nv_bfloat16* Qg = g_qh + ((size_t)bh * NN + q0) * DP;
        for (int idx = tid; idx < AQT * 10; idx += 256) {
            int r = idx / 10, c = idx - r * 10;
            *(uint4*)(sQ + r * KSTR + c * 8) = *(const uint4*)(Qg + r * DP + c * 8);
        }
        __syncthreads();
#pragma unroll
        for (int kc = 0; kc < 5; kc++)
            LDSM4(qh[kc][0], qh[kc][1], qh[kc][2], qh[kc][3], bK0 + aoff + kc * 32);
        __syncthreads();
        const __nv_bfloat16* Qg2 = g_ql + ((size_t)bh * NN + q0) * DP;
        for (int idx = tid; idx < AQT * 10; idx += 256) {
            int r = idx / 10, c = idx - r * 10;
            *(uint4*)(sQ + r * KSTR + c * 8) = *(const uint4*)(Qg2 + r * DP + c * 8);
        }
        __syncthreads();
#pragma unroll
        for (int kc = 0; kc < 5; kc++)
            LDSM4(ql[kc][0], ql[kc][1], ql[kc][2], ql[kc][3], bK0 + aoff + kc * 32);
    }

    float accO[10][4];
#pragma unroll
    for (int i = 0; i < 10; i++)
#pragma unroll
        for (int r = 0; r < 4; r++) accO[i][r] = 0.f;
    float mr0 = -1e30f, mr1 = -1e30f, lr0 = 0.f, lr1 = 0.f;

    for (int kt0 = 0; kt0 < NN; kt0 += AKT) {
        __syncthreads();
        for (int idx = tid; idx < AKT * 10; idx += 256) {
            int r = idx / 10, c = idx - r * 10;
            size_t go = ((size_t)bh * NN + kt0 + r) * DP + c * 8;
            *(uint4*)(&sK[0][r * KSTR + c * 8]) = *(const uint4*)(g_kh + go);
            *(uint4*)(&sK[1][r * KSTR + c * 8]) = *(const uint4*)(g_kl + go);
        }
        for (int idx = tid; idx < DP * 8; idx += 256) {
            int r = idx >> 3, c = idx & 7;
            size_t go = ((size_t)bh * DP + r) * NN + kt0 + c * 8;
            *(uint4*)(&sV[0][r * VSTR + c * 8]) = *(const uint4*)(g_vth + go);
            *(uint4*)(&sV[1][r * VSTR + c * 8]) = *(const uint4*)(g_vtl + go);
        }
        if (tid < AKT) {
            float pos = (float)(kt0 + tid) * (1.0f / (NN - 1));
            float dd = pos - 0.5f;
            psc[tid] = scl * __expf(-sf * dd * dd);
        }
        __syncthreads();

        // ---- S = Q K^T, 3-pass split ----
        float sacc[8][4];
#pragma unroll
        for (int i = 0; i < 8; i++)
#pragma unroll
            for (int r = 0; r < 4; r++) sacc[i][r] = 0.f;
#pragma unroll
        for (int kc = 0; kc < 5; kc++) {
            uint32_t kadd = kc * 32;
#pragma unroll
            for (int nfp = 0; nfp < 4; nfp++) {
                uint32_t kbh[4], kbl[4];
                LDSM4(kbh[0], kbh[1], kbh[2], kbh[3], bK0 + boffS[nfp] + kadd);
                LDSM4(kbl[0], kbl[1], kbl[2], kbl[3], bK1 + boffS[nfp] + kadd);
#pragma unroll
                for (int sub = 0; sub < 2; sub++) {
                    int nf = nfp * 2 + sub;
                    MMA16816(sacc[nf], qh[kc], kbh + 2 * sub);
                    MMA16816(sacc[nf], qh[kc], kbl + 2 * sub);
                    MMA16816(sacc[nf], ql[kc], kbh + 2 * sub);
                }
            }
        }

        // ---- pos-scale + online softmax ----
        float tm0 = -1e30f, tm1 = -1e30f;
#pragma unroll
        for (int nf = 0; nf < 8; nf++) {
            int c0 = nf * 8 + 2 * (lane & 3);
            float p0 = psc[c0], p1 = psc[c0 + 1];
            sacc[nf][0] *= p0; sacc[nf][1] *= p1;
            sacc[nf][2] *= p0; sacc[nf][3] *= p1;
            tm0 = fmaxf(tm0, fmaxf(sacc[nf][0], sacc[nf][1]));
            tm1 = fmaxf(tm1, fmaxf(sacc[nf][2], sacc[nf][3]));
        }
        tm0 = fmaxf(tm0, __shfl_xor_sync(0xffffffffu, tm0, 1));
        tm0 = fmaxf(tm0, __shfl_xor_sync(0xffffffffu, tm0, 2));
        tm1 = fmaxf(tm1, __shfl_xor_sync(0xffffffffu, tm1, 1));
        tm1 = fmaxf(tm1, __shfl_xor_sync(0xffffffffu, tm1, 2));
        float mn0 = fmaxf(mr0, tm0), mn1 = fmaxf(mr1, tm1);
        float corr0 = __expf(mr0 - mn0), corr1 = __expf(mr1 - mn1);
        float s0 = 0.f, s1 = 0.f;
#pragma unroll
        for (int nf = 0; nf < 8; nf++) {
            sacc[nf][0] = __expf(sacc[nf][0] - mn0);
            sacc[nf][1] = __expf(sacc[nf][1] - mn0);
            sacc[nf][2] = __expf(sacc[nf][2] - mn1);
            sacc[nf][3] = __expf(sacc[nf][3] - mn1);
            s0 += sacc[nf][0] + sacc[nf][1];
            s1 += sacc[nf][2] + sacc[nf][3];
        }
        s0 += __shfl_xor_sync(0xffffffffu, s0, 1);
        s0 += __shfl_xor_sync(0xffffffffu, s0, 2);
        s1 += __shfl_xor_sync(0xffffffffu, s1, 1);
        s1 += __shfl_xor_sync(0xffffffffu, s1, 2);
        lr0 = lr0 * corr0 + s0;
        lr1 = lr1 * corr1 + s1;
        mr0 = mn0; mr1 = mn1;
#pragma unroll
        for (int nf = 0; nf < 10; nf++) {
            accO[nf][0] *= corr0; accO[nf][1] *= corr0;
            accO[nf][2] *= corr1; accO[nf][3] *= corr1;
        }

        // ---- pack P into A-frags (hi/lo) ----
        uint32_t pAh[4][4], pAl[4][4];
#pragma unroll
        for (int g = 0; g < 4; g++) {
            packsplit(&pAh[g][0], &pAl[g][0], sacc[2 * g][0], sacc[2 * g][1]);
            packsplit(&pAh[g][1], &pAl[g][1], sacc[2 * g][2], sacc[2 * g][3]);
            packsplit(&pAh[g][2], &pAl[g][2], sacc[2 * g + 1][0], sacc[2 * g + 1][1]);
            packsplit(&pAh[g][3], &pAl[g][3], sacc[2 * g + 1][2], sacc[2 * g + 1][3]);
        }

        // ---- O += P V, 3-pass split ----
#pragma unroll
        for (int kk = 0; kk < 4; kk++) {
            uint32_t kadd = kk * 32;
#pragma unroll
            for (int nfp = 0; nfp < 5; nfp++) {
                uint32_t vbh[4], vbl[4];
                LDSM4(vbh[0], vbh[1], vbh[2], vbh[3], bV0 + voffB[nfp] + kadd);
                LDSM4(vbl[0], vbl[1], vbl[2], vbl[3], bV1 + voffB[nfp] + kadd);
#pragma unroll
                for (int sub = 0; sub < 2; sub++) {
                    int nf = nfp * 2 + sub;
                    MMA16816(accO[nf], pAh[kk], vbh + 2 * sub);
                    MMA16816(accO[nf], pAh[kk], vbl + 2 * sub);
                    MMA16816(accO[nf], pAl[kk], vbh + 2 * sub);
                }
            }
        }
    }

    // ---- epilogue: normalize, store bf16 hi/lo into proj-A buffers ----
    float inv0 = 1.0f / lr0, inv1 = 1.0f / lr1;
    int r = lane >> 2;
    int n_0 = q0 + warp * 16 + r;
#pragma unroll
    for (int nf = 0; nf < 10; nf++) {
        int d0 = nf * 8 + 2 * (lane & 3);
        if (d0 + 1 < HD) {
            size_t a0 = ((size_t)(b * NN + n_0)) * CC + h * HD + d0;
            size_t a1 = ((size_t)(b * NN + n_0 + 8)) * CC + h * HD + d0;
            uint32_t hp, lp;
            packsplit(&hp, &lp, accO[nf][0] * inv0, accO[nf][1] * inv0);
            *(uint32_t*)(g_ah + a0) = hp;
            *(uint32_t*)(g_al + a0) = lp;
            packsplit(&hp, &lp, accO[nf][2] * inv1, accO[nf][3] * inv1);
            *(uint32_t*)(g_ah + a1) = hp;
            *(uint32_t*)(g_al + a1) = lp;
        }
    }
}

// ---------------------------------------------------------------------------
extern "C" void kernel_launch(void* const* d_in, const int* in_sizes, int n_in,
                              void* d_out, int out_size) {
    const float* x       = (const float*)d_in[0];
    const float* norm_g  = (const float*)d_in[1];
    const float* norm_b  = (const float*)d_in[2];
    const float* ap_w    = (const float*)d_in[3];
    const float* ap_b    = (const float*)d_in[4];
    const float* norm2_g = (const float*)d_in[5];
    const float* norm2_b = (const float*)d_in[6];
    const float* qkv_w   = (const float*)d_in[7];
    const float* proj_w  = (const float*)d_in[8];
    const float* proj_b  = (const float*)d_in[9];
    const float* scaling = (const float*)d_in[10];
    float* out = (float*)d_out;

    __nv_bfloat16 *p_qbh, *p_qbl, *p_pbh, *p_pbl, *p_ah, *p_al;
    cudaGetSymbolAddress((void**)&p_qbh, g_qbh);
    cudaGetSymbolAddress((void**)&p_qbl, g_qbl);
    cudaGetSymbolAddress((void**)&p_pbh, g_pbh);
    cudaGetSymbolAddress((void**)&p_pbl, g_pbl);
    cudaGetSymbolAddress((void**)&p_ah, g_ah);
    cudaGetSymbolAddress((void**)&p_al, g_al);

    k_ln_joint<<<Bb * NN, CC>>>(x, norm_g, norm_b, ap_w, ap_b);
    k_softmax_seq<<<Bb * JJ, 256>>>();
    k_pool_ln<<<Bb * NN, CC>>>(norm2_g, norm2_b);

    k_cvt_w<<<(QC * CC + 255) / 256, 256>>>(qkv_w, p_qbh, p_qbl, QC * CC);
    k_zero_pad<<<(64 * 1024 * (DP - HD) + 255) / 256, 256>>>();
    k_mma_gemm<<<dim3(13, (Bb * NN) / GBM), 256>>>(p_ah, p_al, p_qbh, p_qbl,
                                                   nullptr, QC, nullptr, 1);
    k_vt<<<dim3(NN / 32, 3, Bb * HH), dim3(32, 8)>>>();

    k_attn_mma<<<dim3(NN / AQT, HH, Bb), 256>>>(scaling);

    k_cvt_w<<<(CC * CC + 255) / 256, 256>>>(proj_w, p_pbh, p_pbl, CC * CC);
    k_mma_gemm<<<dim3(5, (Bb * NN) / GBM), 256>>>(p_ah, p_al, p_pbh, p_pbl,
                                                  out, CC, proj_b, 0);
}

// round 6
// speedup vs baseline: 2.8665x; 1.2549x over previous
#include <cuda_runtime.h>
#include <cuda_bf16.h>
#include <math.h>
#include <stdint.h>

typedef unsigned long long ull;

#define Bb 8
#define NN 1024
#define CC 544
#define JJ 17
#define FF 32
#define HH 8
#define HD 68
#define QC 1632
#define DP 80     // padded head dim

// tensor-core warp ops (family-common PTX, OK on plain sm_103 target)
#define LDSM4(r0,r1,r2,r3,addr) \
    asm volatile("ldmatrix.sync.aligned.m8n8.x4.shared.b16 {%0,%1,%2,%3}, [%4];" \
        : "=r"(r0),"=r"(r1),"=r"(r2),"=r"(r3) : "r"(addr))
#define MMA16816(d,a,b) \
    asm volatile("mma.sync.aligned.m16n8k16.row.col.f32.bf16.bf16.f32 " \
        "{%0,%1,%2,%3}, {%4,%5,%6,%7}, {%8,%9}, {%0,%1,%2,%3};" \
        : "+f"((d)[0]),"+f"((d)[1]),"+f"((d)[2]),"+f"((d)[3]) \
        : "r"((a)[0]),"r"((a)[1]),"r"((a)[2]),"r"((a)[3]), "r"((b)[0]),"r"((b)[1]))
#define CVT2(d, lo, hi) asm("cvt.rn.bf16x2.f32 %0, %1, %2;" : "=r"(d) : "f"(hi), "f"(lo))

#define CP16(dst, src) \
    asm volatile("cp.async.cg.shared.global [%0], [%1], 16;" \
        :: "r"(dst), "l"(src) : "memory")
#define CP16Z(dst, src, sz) \
    asm volatile("cp.async.cg.shared.global [%0], [%1], 16, %2;" \
        :: "r"(dst), "l"(src), "r"(sz) : "memory")
#define CPCOMMIT() asm volatile("cp.async.commit_group;" ::: "memory")
#define CPWAIT1()  asm volatile("cp.async.wait_group 1;" ::: "memory")
#define CPWAIT0()  asm volatile("cp.async.wait_group 0;" ::: "memory")

__device__ __forceinline__ uint32_t smem_u32(const void* p) {
    uint32_t a;
    asm("{ .reg .u64 t; cvta.to.shared.u64 t, %1; cvt.u32.u64 %0, t; }" : "=r"(a) : "l"(p));
    return a;
}
__device__ __forceinline__ const void* gptr(const void* p) {
    return (const void*)__cvta_generic_to_global(p);
}
__device__ __forceinline__ void packsplit(uint32_t* hp, uint32_t* lp, float v0, float v1) {
    uint32_t h; CVT2(h, v0, v1);
    float l0 = v0 - __uint_as_float(h << 16);
    float l1 = v1 - __uint_as_float(h & 0xffff0000u);
    uint32_t l; CVT2(l, l0, l1);
    *hp = h; *lp = l;
}

// -------- scratch --------
__device__ float g_sc [(size_t)Bb * NN * JJ];
__device__ float g_w  [(size_t)Bb * NN * JJ];
__device__ __nv_bfloat16 g_ah [(size_t)Bb * NN * CC];
__device__ __nv_bfloat16 g_al [(size_t)Bb * NN * CC];
__device__ __nv_bfloat16 g_qbh[(size_t)QC * CC];
__device__ __nv_bfloat16 g_qbl[(size_t)QC * CC];
__device__ __nv_bfloat16 g_pbh[(size_t)CC * CC];
__device__ __nv_bfloat16 g_pbl[(size_t)CC * CC];
__device__ __nv_bfloat16 g_qh [(size_t)Bb * HH * NN * DP];
__device__ __nv_bfloat16 g_ql [(size_t)Bb * HH * NN * DP];
__device__ __nv_bfloat16 g_kh [(size_t)Bb * HH * NN * DP];
__device__ __nv_bfloat16 g_kl [(size_t)Bb * HH * NN * DP];
__device__ __nv_bfloat16 g_vh [(size_t)Bb * HH * NN * DP];
__device__ __nv_bfloat16 g_vl [(size_t)Bb * HH * NN * DP];
__device__ __nv_bfloat16 g_vth[(size_t)Bb * HH * DP * NN];
__device__ __nv_bfloat16 g_vtl[(size_t)Bb * HH * DP * NN];

__device__ __forceinline__ float wsum(float v) {
#pragma unroll
    for (int o = 16; o > 0; o >>= 1) v += __shfl_xor_sync(0xffffffffu, v, o);
    return v;
}
__device__ __forceinline__ float wmax(float v) {
#pragma unroll
    for (int o = 16; o > 0; o >>= 1) v = fmaxf(v, __shfl_xor_sync(0xffffffffu, v, o));
    return v;
}

// ---------------------------------------------------------------------------
// Kernel 1: per-joint LN (not stored) + pooling scores
// ---------------------------------------------------------------------------
__global__ void k_score(const float* __restrict__ x,
                        const float* __restrict__ ng,
                        const float* __restrict__ nb,
                        const float* __restrict__ apw,
                        const float* __restrict__ apb) {
    int bn = blockIdx.x;
    int j = threadIdx.x >> 5;
    int f = threadIdx.x & 31;

    float v = x[(size_t)bn * CC + j * FF + f];
    float mu = wsum(v) * (1.0f / FF);
    float d = v - mu;
    float var = wsum(d * d) * (1.0f / FF);
    float xn = d * rsqrtf(var + 1e-5f) * ng[f] + nb[f];

    float sc = wsum(xn * apw[f]);
    if (f == 0) g_sc[(size_t)bn * JJ + j] = sc + apb[0];
}

// ---------------------------------------------------------------------------
// Kernel 2: softmax over sequence axis N per (b, joint)
// ---------------------------------------------------------------------------
__global__ void k_softmax_seq() {
    int bj = blockIdx.x;
    int b = bj / JJ, j = bj - b * JJ;
    int tid = threadIdx.x;
    const float* base = g_sc + (size_t)b * NN * JJ + j;

    float v[4];
#pragma unroll
    for (int i = 0; i < 4; i++) v[i] = base[(size_t)(tid + i * 256) * JJ];

    __shared__ float red[8];
    __shared__ float bc;
    int wid = tid >> 5, lane = tid & 31;

    float mx = fmaxf(fmaxf(v[0], v[1]), fmaxf(v[2], v[3]));
    mx = wmax(mx);
    if (lane == 0) red[wid] = mx;
    __syncthreads();
    if (tid == 0) {
        float m = red[0];
        for (int i = 1; i < 8; i++) m = fmaxf(m, red[i]);
        bc = m;
    }
    __syncthreads();
    mx = bc;
    __syncthreads();

    float se = 0.f;
#pragma unroll
    for (int i = 0; i < 4; i++) { v[i] = __expf(v[i] - mx); se += v[i]; }
    se = wsum(se);
    if (lane == 0) red[wid] = se;
    __syncthreads();
    if (tid == 0) {
        float s = 0.f;
        for (int i = 0; i < 8; i++) s += red[i];
        bc = 1.0f / s;
    }
    __syncthreads();
    float inv = bc;

    float* wbase = g_w + (size_t)b * NN * JJ + j;
#pragma unroll
    for (int i = 0; i < 4; i++) wbase[(size_t)(tid + i * 256) * JJ] = v[i] * inv;
}

// ---------------------------------------------------------------------------
// Kernel 3: recompute joint-LN from x, pool, LN over C -> bf16 hi/lo
// ---------------------------------------------------------------------------
__global__ void k_pool_ln(const float* __restrict__ x,
                          const float* __restrict__ ng,
                          const float* __restrict__ nb,
                          const float* __restrict__ g2,
                          const float* __restrict__ b2) {
    int bn = blockIdx.x;
    int c = threadIdx.x;
    int wid = c >> 5, lane = c & 31;        // wid = joint, lane = feature
    __shared__ float red[17];
    __shared__ float bc0, bc1;

    float xv = x[(size_t)bn * CC + c];
    float mu_j = wsum(xv) * (1.0f / FF);
    float dj = xv - mu_j;
    float var_j = wsum(dj * dj) * (1.0f / FF);
    float xn = dj * rsqrtf(var_j + 1e-5f) * ng[lane] + nb[lane];

    float v = xn * g_w[(size_t)bn * JJ + wid];

    float s = wsum(v);
    if (lane == 0) red[wid] = s;
    __syncthreads();
    if (wid == 0) {
        float t = (lane < 17) ? red[lane] : 0.f;
        t = wsum(t);
        if (lane == 0) bc0 = t * (1.0f / CC);
    }
    __syncthreads();
    float mu = bc0;
    float d = v - mu;

    float s2 = wsum(d * d);
    if (lane == 0) red[wid] = s2;
    __syncthreads();
    if (wid == 0) {
        float t = (lane < 17) ? red[lane] : 0.f;
        t = wsum(t);
        if (lane == 0) bc1 = t * (1.0f / CC);
    }
    __syncthreads();
    float var = bc1;

    float xp = d * rsqrtf(var + 1e-5f) * g2[c] + b2[c];
    __nv_bfloat16 h = __float2bfloat16(xp);
    __nv_bfloat16 l = __float2bfloat16(xp - __bfloat162float(h));
    size_t o = (size_t)bn * CC + c;
    g_ah[o] = h; g_al[o] = l;
}

// ---------------------------------------------------------------------------
// Weight conversion fp32 -> bf16 hi/lo (vectorized x4)
// ---------------------------------------------------------------------------
__global__ void k_cvt_w(const float* __restrict__ W,
                        __nv_bfloat16* __restrict__ bh,
                        __nv_bfloat16* __restrict__ bl,
                        int total4) {
    int idx = blockIdx.x * 256 + threadIdx.x;
    if (idx >= total4) return;
    float4 v = ((const float4*)W)[idx];
    uint32_t h0, l0, h1, l1;
    packsplit(&h0, &l0, v.x, v.y);
    packsplit(&h1, &l1, v.z, v.w);
    ((uint2*)bh)[idx] = make_uint2(h0, h1);
    ((uint2*)bl)[idx] = make_uint2(l0, l1);
}

// ---------------------------------------------------------------------------
// Zero the d-pad region (68..79) of Q/K/V operand buffers
// ---------------------------------------------------------------------------
__global__ void k_zero_pad() {
    int idx = blockIdx.x * 256 + threadIdx.x;
    if (idx >= 64 * 1024 * (DP - HD)) return;
    int bhn = idx / (DP - HD), d = HD + (idx - bhn * (DP - HD));
    size_t ad = (size_t)bhn * DP + d;
    __nv_bfloat16 z = __float2bfloat16(0.f);
    g_qh[ad] = z; g_ql[ad] = z;
    g_kh[ad] = z; g_kl[ad] = z;
    g_vh[ad] = z; g_vl[ad] = z;
}

// ---------------------------------------------------------------------------
// V transpose: [bh][n][DP] -> [bh][d][n]
// ---------------------------------------------------------------------------
__global__ void k_vt() {
    __shared__ __nv_bfloat16 t0[32][33], t1[32][33];
    int n0 = blockIdx.x * 32, d0 = blockIdx.y * 32, bh = blockIdx.z;
    int tx = threadIdx.x, ty = threadIdx.y;
    int d = d0 + tx;
#pragma unroll
    for (int i = 0; i < 4; i++) {
        int n = n0 + ty + i * 8;
        if (d < DP) {
            t0[ty + i * 8][tx] = g_vh[((size_t)bh * NN + n) * DP + d];
            t1[ty + i * 8][tx] = g_vl[((size_t)bh * NN + n) * DP + d];
        }
    }
    __syncthreads();
#pragma unroll
    for (int i = 0; i < 4; i++) {
        int dd = d0 + ty + i * 8;
        if (dd < DP) {
            g_vth[((size_t)bh * DP + dd) * NN + n0 + tx] = t0[tx][ty + i * 8];
            g_vtl[((size_t)bh * DP + dd) * NN + n0 + tx] = t1[tx][ty + i * 8];
        }
    }
}

// ---------------------------------------------------------------------------
// cp.async double-buffered mma.sync bf16-split GEMM.
// mode 0: fp32 C (+bias). mode 1: scatter QKV.
// ---------------------------------------------------------------------------
#define GBM 128
#define GBN 128
#define GBK 32
#define SST 40
#define CH_H (GBM * SST)       // 5120 halves per sub-array
#define STG_H (4 * CH_H)       // halves per stage
#define GEMM_SMEM (2 * STG_H * 2)   // bytes = 81920

__global__ void __launch_bounds__(256) k_mma_gemm(
        const __nv_bfloat16* __restrict__ Ah, const __nv_bfloat16* __restrict__ Al,
        const __nv_bfloat16* __restrict__ Bh, const __nv_bfloat16* __restrict__ Bl,
        float* __restrict__ Cm, int Nn, const float* __restrict__ bias, int mode) {
    extern __shared__ __nv_bfloat16 dyn[];
    int tid = threadIdx.x;
    int lane = tid & 31, warp = tid >> 5;
    int wm = warp >> 1, wn = warp & 1;
    int m0 = blockIdx.y * GBM, n0 = blockIdx.x * GBN;
    uint32_t base = smem_u32(dyn);

    float acc[2][8][4];
#pragma unroll
    for (int i = 0; i < 2; i++)
#pragma unroll
        for (int j = 0; j < 8; j++)
#pragma unroll
            for (int r = 0; r < 4; r++) acc[i][j][r] = 0.f;

    uint32_t aoff[2];
#pragma unroll
    for (int mf = 0; mf < 2; mf++)
        aoff[mf] = (uint32_t)(((wm * 32 + mf * 16 + (lane & 15)) * SST + 8 * (lane >> 4)) * 2);
    uint32_t boff[4];
#pragma unroll
    for (int nfp = 0; nfp < 4; nfp++)
        boff[nfp] = (uint32_t)(((wn * 64 + nfp * 16 + (lane & 7) + 8 * (lane >> 4)) * SST
                                + 8 * ((lane >> 3) & 1)) * 2);

    int lrow = tid >> 2;
    int lc = (tid & 3) * 8;

#define GISSUE(ck, st) do { \
    int kb_ = (ck) * GBK; \
    uint32_t sb_ = base + (uint32_t)((st) * STG_H * 2); \
    _Pragma("unroll") \
    for (int half_ = 0; half_ < 2; half_++) { \
        int row_ = lrow + half_ * 64; \
        uint32_t do_ = (uint32_t)((row_ * SST + lc) * 2); \
        CP16(sb_ + do_, gptr(Ah + (size_t)(m0 + row_) * CC + kb_ + lc)); \
        CP16(sb_ + (uint32_t)(CH_H * 2) + do_, gptr(Al + (size_t)(m0 + row_) * CC + kb_ + lc)); \
        int ok_ = (n0 + row_ < Nn) ? 16 : 0; \
        int br_ = (n0 + row_ < Nn) ? row_ : 0; \
        CP16Z(sb_ + (uint32_t)(2 * CH_H * 2) + do_, gptr(Bh + (size_t)(n0 + br_) * CC + kb_ + lc), ok_); \
        CP16Z(sb_ + (uint32_t)(3 * CH_H * 2) + do_, gptr(Bl + (size_t)(n0 + br_) * CC + kb_ + lc), ok_); \
    } \
} while (0)

    GISSUE(0, 0);
    CPCOMMIT();

    for (int ck = 0; ck < 17; ck++) {
        if (ck < 16) {
            GISSUE(ck + 1, (ck + 1) & 1);
            CPCOMMIT();
            CPWAIT1();
        } else {
            CPWAIT0();
        }
        __syncthreads();

        uint32_t sb = base + (uint32_t)((ck & 1) * STG_H * 2);
        uint32_t bAh = sb, bAl = sb + CH_H * 2;
        uint32_t bBh = sb + 2 * CH_H * 2, bBl = sb + 3 * CH_H * 2;
#pragma unroll
        for (int ks = 0; ks < 2; ks++) {
            uint32_t kadd = (uint32_t)(ks * 16 * 2);
            uint32_t ah[2][4], al[2][4];
#pragma unroll
            for (int mf = 0; mf < 2; mf++) {
                LDSM4(ah[mf][0], ah[mf][1], ah[mf][2], ah[mf][3], bAh + aoff[mf] + kadd);
                LDSM4(al[mf][0], al[mf][1], al[mf][2], al[mf][3], bAl + aoff[mf] + kadd);
            }
#pragma unroll
            for (int nfp = 0; nfp < 4; nfp++) {
                uint32_t bh4[4], bl4[4];
                LDSM4(bh4[0], bh4[1], bh4[2], bh4[3], bBh + boff[nfp] + kadd);
                LDSM4(bl4[0], bl4[1], bl4[2], bl4[3], bBl + boff[nfp] + kadd);
#pragma unroll
                for (int mf = 0; mf < 2; mf++)
#pragma unroll
                    for (int sub = 0; sub < 2; sub++) {
                        int nf = nfp * 2 + sub;
                        MMA16816(acc[mf][nf], ah[mf], bh4 + 2 * sub);
                        MMA16816(acc[mf][nf], ah[mf], bl4 + 2 * sub);
                        MMA16816(acc[mf][nf], al[mf], bh4 + 2 * sub);
                    }
            }
        }
        __syncthreads();
    }
#undef GISSUE

    if (mode == 0) {
#pragma unroll
        for (int mf = 0; mf < 2; mf++) {
            int r0 = m0 + wm * 32 + mf * 16 + (lane >> 2);
#pragma unroll
            for (int nf = 0; nf < 8; nf++) {
                int col = n0 + wn * 64 + nf * 8 + 2 * (lane & 3);
                if (col < Nn) {
                    float b0 = bias ? bias[col] : 0.f;
                    float b1 = bias ? bias[col + 1] : 0.f;
                    *(float2*)(Cm + (size_t)r0 * Nn + col) =
                        make_float2(acc[mf][nf][0] + b0, acc[mf][nf][1] + b1);
                    *(float2*)(Cm + (size_t)(r0 + 8) * Nn + col) =
                        make_float2(acc[mf][nf][2] + b0, acc[mf][nf][3] + b1);
                }
            }
        }
    } else {
#pragma unroll
        for (int mf = 0; mf < 2; mf++) {
            int r0 = m0 + wm * 32 + mf * 16 + (lane >> 2);
#pragma unroll
            for (int nf = 0; nf < 8; nf++) {
                int col = n0 + wn * 64 + nf * 8 + 2 * (lane & 3);
                if (col < QC) {
                    int s = (col >= 1088) ? 2 : (col >= 544 ? 1 : 0);
                    int rem = col - s * 544;
                    int hh = rem / 68;
                    int d = rem - hh * 68;
                    __nv_bfloat16* Dh = (s == 0) ? g_qh : (s == 1) ? g_kh : g_vh;
                    __nv_bfloat16* Dl = (s == 0) ? g_ql : (s == 1) ? g_kl : g_vl;
#pragma unroll
                    for (int rr = 0; rr < 2; rr++) {
                        int row = r0 + rr * 8;
                        int bb = row >> 10, nn = row & 1023;
                        size_t ad = ((size_t)(bb * HH + hh) * NN + nn) * DP + d;
                        uint32_t hp, lp;
                        packsplit(&hp, &lp, acc[mf][nf][rr * 2], acc[mf][nf][rr * 2 + 1]);
                        *(uint32_t*)(Dh + ad) = hp;
                        *(uint32_t*)(Dl + ad) = lp;
                    }
                }
            }
        }
    }
}

// ---------------------------------------------------------------------------
// Flash attention, mma.sync bf16 split, cp.async double-buffered K/V tiles.
// ---------------------------------------------------------------------------
#define AQT 128
#define AKT 64
#define KSTR 88
#define VSTR 72
#define A_KH 0
#define A_KL (AKT * KSTR)                 // 5632
#define A_VH (2 * AKT * KSTR)             // 11264
#define A_VL (2 * AKT * KSTR + DP * VSTR) // 17024
#define ASTG_H (2 * AKT * KSTR + 2 * DP * VSTR)  // 22784 halves
#define ATTN_SMEM (2 * ASTG_H * 2)        // 91136 bytes

__global__ void __launch_bounds__(256) k_attn_mma(const float* __restrict__ sf_ptr) {
    extern __shared__ __nv_bfloat16 adyn[];
    __shared__ float psc[2][AKT];

    int tid = threadIdx.x, lane = tid & 31, warp = tid >> 5;
    int b = blockIdx.z, h = blockIdx.y, q0 = blockIdx.x * AQT;
    int bh = b * HH + h;
    uint32_t abase = smem_u32(adyn);

    const float sf = sf_ptr[0];
    const float scl = rsqrtf((float)HD);

    uint32_t aoff = (uint32_t)(((warp * 16 + (lane & 15)) * KSTR + 8 * (lane >> 4)) * 2);
    uint32_t boffS[4], voffB[5];
#pragma unroll
    for (int nfp = 0; nfp < 4; nfp++)
        boffS[nfp] = (uint32_t)(((nfp * 16 + (lane & 7) + 8 * (lane >> 4)) * KSTR
                                 + 8 * ((lane >> 3) & 1)) * 2);
#pragma unroll
    for (int nfp = 0; nfp < 5; nfp++)
        voffB[nfp] = (uint32_t)(((nfp * 16 + (lane & 7) + 8 * (lane >> 4)) * VSTR
                                 + 8 * ((lane >> 3) & 1)) * 2);

    // ---- stage Q hi then lo through smem, extract A-frags ----
    uint32_t qh[5][4], ql[5][4];
    {
        const __nv_bfloat16* Qg = g_qh + ((size_t)bh * NN + q0) * DP;
        for (int idx = tid; idx < AQT * 10; idx += 256) {
            int r = idx / 10, c = idx - r * 10;
            *(uint4*)(adyn + r * KSTR + c * 8) = *(const uint4*)(Qg + r * DP + c * 8);
        }
        __syncthreads();
#pragma unroll
        for (int kc = 0; kc < 5; kc++)
            LDSM4(qh[kc][0], qh[kc][1], qh[kc][2], qh[kc][3], abase + aoff + kc * 32);
        __syncthreads();
        const __nv_bfloat16* Qg2 = g_ql + ((size_t)bh * NN + q0) * DP;
        for (int idx = tid; idx < AQT * 10; idx += 256) {
            int r = idx / 10, c = idx - r * 10;
            *(uint4*)(adyn + r * KSTR + c * 8) = *(const uint4*)(Qg2 + r * DP + c * 8);
        }
        __syncthreads();
#pragma unroll
        for (int kc = 0; kc < 5; kc++)
            LDSM4(ql[kc][0], ql[kc][1], ql[kc][2], ql[kc][3], abase + aoff + kc * 32);
        __syncthreads();     // Q region is reused by the K/V pipeline below
    }

    float accO[10][4];
#pragma unroll
    for (int i = 0; i < 10; i++)
#pragma unroll
        for (int r = 0; r < 4; r++) accO[i][r] = 0.f;
    float mr0 = -1e30f, mr1 = -1e30f, lr0 = 0.f, lr1 = 0.f;

#define AISSUE(kt_, st) do { \
    uint32_t sb_ = abase + (uint32_t)((st) * ASTG_H * 2); \
    for (int idx = tid; idx < AKT * 10; idx += 256) { \
        int r_ = idx / 10, c_ = idx - r_ * 10; \
        size_t go_ = ((size_t)bh * NN + (kt_) + r_) * DP + c_ * 8; \
        uint32_t do_ = (uint32_t)((r_ * KSTR + c_ * 8) * 2); \
        CP16(sb_ + do_, gptr(g_kh + go_)); \
        CP16(sb_ + (uint32_t)(A_KL * 2) + do_, gptr(g_kl + go_)); \
    } \
    for (int idx = tid; idx < DP * 8; idx += 256) { \
        int r_ = idx >> 3, c_ = idx & 7; \
        size_t go_ = ((size_t)bh * DP + r_) * NN + (kt_) + c_ * 8; \
        uint32_t do_ = (uint32_t)((r_ * VSTR + c_ * 8) * 2); \
        CP16(sb_ + (uint32_t)(A_VH * 2) + do_, gptr(g_vth + go_)); \
        CP16(sb_ + (uint32_t)(A_VL * 2) + do_, gptr(g_vtl + go_)); \
    } \
    if (tid < AKT) { \
        float pos_ = (float)((kt_) + tid) * (1.0f / (NN - 1)); \
        float dd_ = pos_ - 0.5f; \
        psc[st][tid] = scl * __expf(-sf * dd_ * dd_); \
    } \
} while (0)

    AISSUE(0, 0);
    CPCOMMIT();

    for (int t = 0; t < 16; t++) {
        if (t < 15) {
            AISSUE((t + 1) * AKT, (t + 1) & 1);
            CPCOMMIT();
            CPWAIT1();
        } else {
            CPWAIT0();
        }
        __syncthreads();

        int st = t & 1;
        uint32_t sb = abase + (uint32_t)(st * ASTG_H * 2);
        uint32_t bK0 = sb, bK1 = sb + A_KL * 2;
        uint32_t bV0 = sb + A_VH * 2, bV1 = sb + A_VL * 2;

        // ---- S = Q K^T, 3-pass split ----
        float sacc[8][4];
#pragma unroll
        for (int i = 0; i < 8; i++)
#pragma unroll
            for (int r = 0; r < 4; r++) sacc[i][r] = 0.f;
#pragma unroll
        for (int kc = 0; kc < 5; kc++) {
            uint32_t kadd = kc * 32;
#pragma unroll
            for (int nfp = 0; nfp < 4; nfp++) {
                uint32_t kbh[4], kbl[4];
                LDSM4(kbh[0], kbh[1], kbh[2], kbh[3], bK0 + boffS[nfp] + kadd);
                LDSM4(kbl[0], kbl[1], kbl[2], kbl[3], bK1 + boffS[nfp] + kadd);
#pragma unroll
                for (int sub = 0; sub < 2; sub++) {
                    int nf = nfp * 2 + sub;
                    MMA16816(sacc[nf], qh[kc], kbh + 2 * sub);
                    MMA16816(sacc[nf], qh[kc], kbl + 2 * sub);
                    MMA16816(sacc[nf], ql[kc], kbh + 2 * sub);
                }
            }
        }

        // ---- pos-scale + online softmax ----
        float tm0 = -1e30f, tm1 = -1e30f;
#pragma unroll
        for (int nf = 0; nf < 8; nf++) {
            int c0 = nf * 8 + 2 * (lane & 3);
            float p0 = psc[st][c0], p1 = psc[st][c0 + 1];
            sacc[nf][0] *= p0; sacc[nf][1] *= p1;
            sacc[nf][2] *= p0; sacc[nf][3] *= p1;
            tm0 = fmaxf(tm0, fmaxf(sacc[nf][0], sacc[nf][1]));
            tm1 = fmaxf(tm1, fmaxf(sacc[nf][2], sacc[nf][3]));
        }
        tm0 = fmaxf(tm0, __shfl_xor_sync(0xffffffffu, tm0, 1));
        tm0 = fmaxf(tm0, __shfl_xor_sync(0xffffffffu, tm0, 2));
        tm1 = fmaxf(tm1, __shfl_xor_sync(0xffffffffu, tm1, 1));
        tm1 = fmaxf(tm1, __shfl_xor_sync(0xffffffffu, tm1, 2));
        float mn0 = fmaxf(mr0, tm0), mn1 = fmaxf(mr1, tm1);
        float corr0 = __expf(mr0 - mn0), corr1 = __expf(mr1 - mn1);
        float s0 = 0.f, s1 = 0.f;
#pragma unroll
        for (int nf = 0; nf < 8; nf++) {
            sacc[nf][0] = __expf(sacc[nf][0] - mn0);
            sacc[nf][1] = __expf(sacc[nf][1] - mn0);
            sacc[nf][2] = __expf(sacc[nf][2] - mn1);
            sacc[nf][3] = __expf(sacc[nf][3] - mn1);
            s0 += sacc[nf][0] + sacc[nf][1];
            s1 += sacc[nf][2] + sacc[nf][3];
        }
        s0 += __shfl_xor_sync(0xffffffffu, s0, 1);
        s0 += __shfl_xor_sync(0xffffffffu, s0, 2);
        s1 += __shfl_xor_sync(0xffffffffu, s1, 1);
        s1 += __shfl_xor_sync(0xffffffffu, s1, 2);
        lr0 = lr0 * corr0 + s0;
        lr1 = lr1 * corr1 + s1;
        mr0 = mn0; mr1 = mn1;
#pragma unroll
        for (int nf = 0; nf < 10; nf++) {
            accO[nf][0] *= corr0; accO[nf][1] *= corr0;
            accO[nf][2] *= corr1; accO[nf][3] *= corr1;
        }

        // ---- pack P into A-frags (hi/lo) ----
        uint32_t pAh[4][4], pAl[4][4];
#pragma unroll
        for (int g = 0; g < 4; g++) {
            packsplit(&pAh[g][0], &pAl[g][0], sacc[2 * g][0], sacc[2 * g][1]);
            packsplit(&pAh[g][1], &pAl[g][1], sacc[2 * g][2], sacc[2 * g][3]);
            packsplit(&pAh[g][2], &pAl[g][2], sacc[2 * g + 1][0], sacc[2 * g + 1][1]);
            packsplit(&pAh[g][3], &pAl[g][3], sacc[2 * g + 1][2], sacc[2 * g + 1][3]);
        }

        // ---- O += P V, 3-pass split ----
#pragma unroll
        for (int kk = 0; kk < 4; kk++) {
            uint32_t kadd = kk * 32;
#pragma unroll
            for (int nfp = 0; nfp < 5; nfp++) {
                uint32_t vbh[4], vbl[4];
                LDSM4(vbh[0], vbh[1], vbh[2], vbh[3], bV0 + voffB[nfp] + kadd);
                LDSM4(vbl[0], vbl[1], vbl[2], vbl[3], bV1 + voffB[nfp] + kadd);
#pragma unroll
                for (int sub = 0; sub < 2; sub++) {
                    int nf = nfp * 2 + sub;
                    MMA16816(accO[nf], pAh[kk], vbh + 2 * sub);
                    MMA16816(accO[nf], pAh[kk], vbl + 2 * sub);
                    MMA16816(accO[nf], pAl[kk], vbh + 2 * sub);
                }
            }
        }
        __syncthreads();
    }
#undef AISSUE

    // ---- epilogue: normalize, store bf16 hi/lo into proj-A buffers ----
    float inv0 = 1.0f / lr0, inv1 = 1.0f / lr1;
    int r = lane >> 2;
    int n_0 = q0 + warp * 16 + r;
#pragma unroll
    for (int nf = 0; nf < 10; nf++) {
        int d0 = nf * 8 + 2 * (lane & 3);
        if (d0 + 1 < HD) {
            size_t a0 = ((size_t)(b * NN + n_0)) * CC + h * HD + d0;
            size_t a1 = ((size_t)(b * NN + n_0 + 8)) * CC + h * HD + d0;
            uint32_t hp, lp;
            packsplit(&hp, &lp, accO[nf][0] * inv0, accO[nf][1] * inv0);
            *(uint32_t*)(g_ah + a0) = hp;
            *(uint32_t*)(g_al + a0) = lp;
            packsplit(&hp, &lp, accO[nf][2] * inv1, accO[nf][3] * inv1);
            *(uint32_t*)(g_ah + a1) = hp;
            *(uint32_t*)(g_al + a1) = lp;
        }
    }
}

// ---------------------------------------------------------------------------
extern "C" void kernel_launch(void* const* d_in, const int* in_sizes, int n_in,
                              void* d_out, int out_size) {
    const float* x       = (const float*)d_in[0];
    const float* norm_g  = (const float*)d_in[1];
    const float* norm_b  = (const float*)d_in[2];
    const float* ap_w    = (const float*)d_in[3];
    const float* ap_b    = (const float*)d_in[4];
    const float* norm2_g = (const float*)d_in[5];
    const float* norm2_b = (const float*)d_in[6];
    const float* qkv_w   = (const float*)d_in[7];
    const float* proj_w  = (const float*)d_in[8];
    const float* proj_b  = (const float*)d_in[9];
    const float* scaling = (const float*)d_in[10];
    float* out = (float*)d_out;

    static int attr_set = 0;
    if (!attr_set) {
        cudaFuncSetAttribute(k_mma_gemm, cudaFuncAttributeMaxDynamicSharedMemorySize, GEMM_SMEM);
        cudaFuncSetAttribute(k_attn_mma, cudaFuncAttributeMaxDynamicSharedMemorySize, ATTN_SMEM);
        attr_set = 1;
    }

    __nv_bfloat16 *p_qbh, *p_qbl, *p_pbh, *p_pbl, *p_ah, *p_al;
    cudaGetSymbolAddress((void**)&p_qbh, g_qbh);
    cudaGetSymbolAddress((void**)&p_qbl, g_qbl);
    cudaGetSymbolAddress((void**)&p_pbh, g_pbh);
    cudaGetSymbolAddress((void**)&p_pbl, g_pbl);
    cudaGetSymbolAddress((void**)&p_ah, g_ah);
    cudaGetSymbolAddress((void**)&p_al, g_al);

    k_score<<<Bb * NN, CC>>>(x, norm_g, norm_b, ap_w, ap_b);
    k_softmax_seq<<<Bb * JJ, 256>>>();
    k_pool_ln<<<Bb * NN, CC>>>(x, norm_g, norm_b, norm2_g, norm2_b);

    k_cvt_w<<<(QC * CC / 4 + 255) / 256, 256>>>(qkv_w, p_qbh, p_qbl, QC * CC / 4);
    k_zero_pad<<<(64 * 1024 * (DP - HD) + 255) / 256, 256>>>();
    k_mma_gemm<<<dim3(13, (Bb * NN) / GBM), 256, GEMM_SMEM>>>(
        p_ah, p_al, p_qbh, p_qbl, nullptr, QC, nullptr, 1);
    k_vt<<<dim3(NN / 32, 3, Bb * HH), dim3(32, 8)>>>();

    k_attn_mma<<<dim3(NN / AQT, HH, Bb), 256, ATTN_SMEM>>>(scaling);

    k_cvt_w<<<(CC * CC / 4 + 255) / 256, 256>>>(proj_w, p_pbh, p_pbl, CC * CC / 4);
    k_mma_gemm<<<dim3(5, (Bb * NN) / GBM), 256, GEMM_SMEM>>>(
        p_ah, p_al, p_pbh, p_pbl, out, CC, proj_b, 0);
}

// round 7
// speedup vs baseline: 2.9747x; 1.0377x over previous
#include <cuda_runtime.h>
#include <cuda_bf16.h>
#include <math.h>
#include <stdint.h>

typedef unsigned long long ull;

#define Bb 8
#define NN 1024
#define CC 544
#define JJ 17
#define FF 32
#define HH 8
#define HD 68
#define QC 1632
#define DP 80     // padded head dim

// tensor-core warp ops (family-common PTX, OK on plain sm_103 target)
#define LDSM4(r0,r1,r2,r3,addr) \
    asm volatile("ldmatrix.sync.aligned.m8n8.x4.shared.b16 {%0,%1,%2,%3}, [%4];" \
        : "=r"(r0),"=r"(r1),"=r"(r2),"=r"(r3) : "r"(addr))
#define LDSM4T(r0,r1,r2,r3,addr) \
    asm volatile("ldmatrix.sync.aligned.m8n8.x4.trans.shared.b16 {%0,%1,%2,%3}, [%4];" \
        : "=r"(r0),"=r"(r1),"=r"(r2),"=r"(r3) : "r"(addr))
#define MMA16816(d,a,b) \
    asm volatile("mma.sync.aligned.m16n8k16.row.col.f32.bf16.bf16.f32 " \
        "{%0,%1,%2,%3}, {%4,%5,%6,%7}, {%8,%9}, {%0,%1,%2,%3};" \
        : "+f"((d)[0]),"+f"((d)[1]),"+f"((d)[2]),"+f"((d)[3]) \
        : "r"((a)[0]),"r"((a)[1]),"r"((a)[2]),"r"((a)[3]), "r"((b)[0]),"r"((b)[1]))
#define CVT2(d, lo, hi) asm("cvt.rn.bf16x2.f32 %0, %1, %2;" : "=r"(d) : "f"(hi), "f"(lo))

#define CP16(dst, src) \
    asm volatile("cp.async.cg.shared.global [%0], [%1], 16;" \
        :: "r"(dst), "l"(src) : "memory")
#define CP16Z(dst, src, sz) \
    asm volatile("cp.async.cg.shared.global [%0], [%1], 16, %2;" \
        :: "r"(dst), "l"(src), "r"(sz) : "memory")
#define CPCOMMIT() asm volatile("cp.async.commit_group;" ::: "memory")
#define CPWAIT1()  asm volatile("cp.async.wait_group 1;" ::: "memory")
#define CPWAIT0()  asm volatile("cp.async.wait_group 0;" ::: "memory")

__device__ __forceinline__ uint32_t smem_u32(const void* p) {
    uint32_t a;
    asm("{ .reg .u64 t; cvta.to.shared.u64 t, %1; cvt.u32.u64 %0, t; }" : "=r"(a) : "l"(p));
    return a;
}
__device__ __forceinline__ const void* gptr(const void* p) {
    return (const void*)__cvta_generic_to_global(p);
}
__device__ __forceinline__ void packsplit(uint32_t* hp, uint32_t* lp, float v0, float v1) {
    uint32_t h; CVT2(h, v0, v1);
    float l0 = v0 - __uint_as_float(h << 16);
    float l1 = v1 - __uint_as_float(h & 0xffff0000u);
    uint32_t l; CVT2(l, l0, l1);
    *hp = h; *lp = l;
}

// -------- scratch --------
__device__ float g_sc [(size_t)Bb * NN * JJ];
__device__ float g_w  [(size_t)Bb * NN * JJ];
__device__ __nv_bfloat16 g_ah [(size_t)Bb * NN * CC];
__device__ __nv_bfloat16 g_al [(size_t)Bb * NN * CC];
__device__ __nv_bfloat16 g_qbh[(size_t)QC * CC];
__device__ __nv_bfloat16 g_qbl[(size_t)QC * CC];
__device__ __nv_bfloat16 g_pbh[(size_t)CC * CC];
__device__ __nv_bfloat16 g_pbl[(size_t)CC * CC];
__device__ __nv_bfloat16 g_qh [(size_t)Bb * HH * NN * DP];
__device__ __nv_bfloat16 g_ql [(size_t)Bb * HH * NN * DP];
__device__ __nv_bfloat16 g_kh [(size_t)Bb * HH * NN * DP];
__device__ __nv_bfloat16 g_kl [(size_t)Bb * HH * NN * DP];
__device__ __nv_bfloat16 g_vh [(size_t)Bb * HH * NN * DP];
__device__ __nv_bfloat16 g_vl [(size_t)Bb * HH * NN * DP];

__device__ __forceinline__ float wsum(float v) {
#pragma unroll
    for (int o = 16; o > 0; o >>= 1) v += __shfl_xor_sync(0xffffffffu, v, o);
    return v;
}
__device__ __forceinline__ float wmax(float v) {
#pragma unroll
    for (int o = 16; o > 0; o >>= 1) v = fmaxf(v, __shfl_xor_sync(0xffffffffu, v, o));
    return v;
}

// ---------------------------------------------------------------------------
// Kernel 1 (fused preprocessing):
//  blocks [0,8192):        per-joint LN + pooling scores
//  blocks [8192,8600):     qkv_w fp32 -> bf16 hi/lo (408 blocks exact)
//  blocks [8600,8736):     proj_w fp32 -> bf16 hi/lo (136 blocks exact)
//  blocks [8736,10182):    zero d-pads of Q/K operand buffers
// ---------------------------------------------------------------------------
#define PRE_SCORE 8192
#define PRE_CVTQ  (PRE_SCORE + 408)
#define PRE_CVTP  (PRE_CVTQ + 136)
#define PRE_PAD   (PRE_CVTP + 1446)

__global__ void k_pre(const float* __restrict__ x,
                      const float* __restrict__ ng,
                      const float* __restrict__ nb,
                      const float* __restrict__ apw,
                      const float* __restrict__ apb,
                      const float* __restrict__ qkv_w,
                      const float* __restrict__ proj_w) {
    int blk = blockIdx.x;
    int tid = threadIdx.x;
    if (blk < PRE_SCORE) {
        int bn = blk;
        int j = tid >> 5, f = tid & 31;
        float v = x[(size_t)bn * CC + j * FF + f];
        float mu = wsum(v) * (1.0f / FF);
        float d = v - mu;
        float var = wsum(d * d) * (1.0f / FF);
        float xn = d * rsqrtf(var + 1e-5f) * ng[f] + nb[f];
        float sc = wsum(xn * apw[f]);
        if (f == 0) g_sc[(size_t)bn * JJ + j] = sc + apb[0];
    } else if (blk < PRE_CVTQ) {
        int idx = (blk - PRE_SCORE) * 544 + tid;    // < 221952 exactly
        float4 v = ((const float4*)qkv_w)[idx];
        uint32_t h0, l0, h1, l1;
        packsplit(&h0, &l0, v.x, v.y);
        packsplit(&h1, &l1, v.z, v.w);
        ((uint2*)g_qbh)[idx] = make_uint2(h0, h1);
        ((uint2*)g_qbl)[idx] = make_uint2(l0, l1);
    } else if (blk < PRE_CVTP) {
        int idx = (blk - PRE_CVTQ) * 544 + tid;     // < 73984 exactly
        float4 v = ((const float4*)proj_w)[idx];
        uint32_t h0, l0, h1, l1;
        packsplit(&h0, &l0, v.x, v.y);
        packsplit(&h1, &l1, v.z, v.w);
        ((uint2*)g_pbh)[idx] = make_uint2(h0, h1);
        ((uint2*)g_pbl)[idx] = make_uint2(l0, l1);
    } else {
        int idx = (blk - PRE_CVTP) * 544 + tid;
        if (idx < 64 * 1024 * (DP - HD)) {
            int bhn = idx / (DP - HD), d = HD + (idx - bhn * (DP - HD));
            size_t ad = (size_t)bhn * DP + d;
            __nv_bfloat16 z = __float2bfloat16(0.f);
            g_qh[ad] = z; g_ql[ad] = z;
            g_kh[ad] = z; g_kl[ad] = z;
        }
    }
}

// ---------------------------------------------------------------------------
// Kernel 2: softmax over sequence axis N per (b, joint)
// ---------------------------------------------------------------------------
__global__ void k_softmax_seq() {
    int bj = blockIdx.x;
    int b = bj / JJ, j = bj - b * JJ;
    int tid = threadIdx.x;
    const float* base = g_sc + (size_t)b * NN * JJ + j;

    float v[4];
#pragma unroll
    for (int i = 0; i < 4; i++) v[i] = base[(size_t)(tid + i * 256) * JJ];

    __shared__ float red[8];
    __shared__ float bc;
    int wid = tid >> 5, lane = tid & 31;

    float mx = fmaxf(fmaxf(v[0], v[1]), fmaxf(v[2], v[3]));
    mx = wmax(mx);
    if (lane == 0) red[wid] = mx;
    __syncthreads();
    if (tid == 0) {
        float m = red[0];
        for (int i = 1; i < 8; i++) m = fmaxf(m, red[i]);
        bc = m;
    }
    __syncthreads();
    mx = bc;
    __syncthreads();

    float se = 0.f;
#pragma unroll
    for (int i = 0; i < 4; i++) { v[i] = __expf(v[i] - mx); se += v[i]; }
    se = wsum(se);
    if (lane == 0) red[wid] = se;
    __syncthreads();
    if (tid == 0) {
        float s = 0.f;
        for (int i = 0; i < 8; i++) s += red[i];
        bc = 1.0f / s;
    }
    __syncthreads();
    float inv = bc;

    float* wbase = g_w + (size_t)b * NN * JJ + j;
#pragma unroll
    for (int i = 0; i < 4; i++) wbase[(size_t)(tid + i * 256) * JJ] = v[i] * inv;
}

// ---------------------------------------------------------------------------
// Kernel 3: recompute joint-LN from x, pool, LN over C -> bf16 hi/lo
// ---------------------------------------------------------------------------
__global__ void k_pool_ln(const float* __restrict__ x,
                          const float* __restrict__ ng,
                          const float* __restrict__ nb,
                          const float* __restrict__ g2,
                          const float* __restrict__ b2) {
    int bn = blockIdx.x;
    int c = threadIdx.x;
    int wid = c >> 5, lane = c & 31;
    __shared__ float red[17];
    __shared__ float bc0, bc1;

    float xv = x[(size_t)bn * CC + c];
    float mu_j = wsum(xv) * (1.0f / FF);
    float dj = xv - mu_j;
    float var_j = wsum(dj * dj) * (1.0f / FF);
    float xn = dj * rsqrtf(var_j + 1e-5f) * ng[lane] + nb[lane];

    float v = xn * g_w[(size_t)bn * JJ + wid];

    float s = wsum(v);
    if (lane == 0) red[wid] = s;
    __syncthreads();
    if (wid == 0) {
        float t = (lane < 17) ? red[lane] : 0.f;
        t = wsum(t);
        if (lane == 0) bc0 = t * (1.0f / CC);
    }
    __syncthreads();
    float mu = bc0;
    float d = v - mu;

    float s2 = wsum(d * d);
    if (lane == 0) red[wid] = s2;
    __syncthreads();
    if (wid == 0) {
        float t = (lane < 17) ? red[lane] : 0.f;
        t = wsum(t);
        if (lane == 0) bc1 = t * (1.0f / CC);
    }
    __syncthreads();
    float var = bc1;

    float xp = d * rsqrtf(var + 1e-5f) * g2[c] + b2[c];
    __nv_bfloat16 h = __float2bfloat16(xp);
    __nv_bfloat16 l = __float2bfloat16(xp - __bfloat162float(h));
    size_t o = (size_t)bn * CC + c;
    g_ah[o] = h; g_al[o] = l;
}

// ---------------------------------------------------------------------------
// cp.async double-buffered mma.sync bf16-split GEMM.
// mode 0: fp32 C (+bias). mode 1: scatter QKV.
// ---------------------------------------------------------------------------
#define GBM 128
#define GBN 128
#define GBK 32
#define SST 40
#define CH_H (GBM * SST)
#define STG_H (4 * CH_H)
#define GEMM_SMEM (2 * STG_H * 2)

__global__ void __launch_bounds__(256) k_mma_gemm(
        const __nv_bfloat16* __restrict__ Ah, const __nv_bfloat16* __restrict__ Al,
        const __nv_bfloat16* __restrict__ Bh, const __nv_bfloat16* __restrict__ Bl,
        float* __restrict__ Cm, int Nn, const float* __restrict__ bias, int mode) {
    extern __shared__ __nv_bfloat16 dyn[];
    int tid = threadIdx.x;
    int lane = tid & 31, warp = tid >> 5;
    int wm = warp >> 1, wn = warp & 1;
    int m0 = blockIdx.y * GBM, n0 = blockIdx.x * GBN;
    uint32_t base = smem_u32(dyn);

    float acc[2][8][4];
#pragma unroll
    for (int i = 0; i < 2; i++)
#pragma unroll
        for (int j = 0; j < 8; j++)
#pragma unroll
            for (int r = 0; r < 4; r++) acc[i][j][r] = 0.f;

    uint32_t aoff[2];
#pragma unroll
    for (int mf = 0; mf < 2; mf++)
        aoff[mf] = (uint32_t)(((wm * 32 + mf * 16 + (lane & 15)) * SST + 8 * (lane >> 4)) * 2);
    uint32_t boff[4];
#pragma unroll
    for (int nfp = 0; nfp < 4; nfp++)
        boff[nfp] = (uint32_t)(((wn * 64 + nfp * 16 + (lane & 7) + 8 * (lane >> 4)) * SST
                                + 8 * ((lane >> 3) & 1)) * 2);

    int lrow = tid >> 2;
    int lc = (tid & 3) * 8;

#define GISSUE(ck, st) do { \
    int kb_ = (ck) * GBK; \
    uint32_t sb_ = base + (uint32_t)((st) * STG_H * 2); \
    _Pragma("unroll") \
    for (int half_ = 0; half_ < 2; half_++) { \
        int row_ = lrow + half_ * 64; \
        uint32_t do_ = (uint32_t)((row_ * SST + lc) * 2); \
        CP16(sb_ + do_, gptr(Ah + (size_t)(m0 + row_) * CC + kb_ + lc)); \
        CP16(sb_ + (uint32_t)(CH_H * 2) + do_, gptr(Al + (size_t)(m0 + row_) * CC + kb_ + lc)); \
        int ok_ = (n0 + row_ < Nn) ? 16 : 0; \
        int br_ = (n0 + row_ < Nn) ? row_ : 0; \
        CP16Z(sb_ + (uint32_t)(2 * CH_H * 2) + do_, gptr(Bh + (size_t)(n0 + br_) * CC + kb_ + lc), ok_); \
        CP16Z(sb_ + (uint32_t)(3 * CH_H * 2) + do_, gptr(Bl + (size_t)(n0 + br_) * CC + kb_ + lc), ok_); \
    } \
} while (0)

    GISSUE(0, 0);
    CPCOMMIT();

    for (int ck = 0; ck < 17; ck++) {
        if (ck < 16) {
            GISSUE(ck + 1, (ck + 1) & 1);
            CPCOMMIT();
            CPWAIT1();
        } else {
            CPWAIT0();
        }
        __syncthreads();

        uint32_t sb = base + (uint32_t)((ck & 1) * STG_H * 2);
        uint32_t bAh = sb, bAl = sb + CH_H * 2;
        uint32_t bBh = sb + 2 * CH_H * 2, bBl = sb + 3 * CH_H * 2;
#pragma unroll
        for (int ks = 0; ks < 2; ks++) {
            uint32_t kadd = (uint32_t)(ks * 16 * 2);
            uint32_t ah[2][4], al[2][4];
#pragma unroll
            for (int mf = 0; mf < 2; mf++) {
                LDSM4(ah[mf][0], ah[mf][1], ah[mf][2], ah[mf][3], bAh + aoff[mf] + kadd);
                LDSM4(al[mf][0], al[mf][1], al[mf][2], al[mf][3], bAl + aoff[mf] + kadd);
            }
#pragma unroll
            for (int nfp = 0; nfp < 4; nfp++) {
                uint32_t bh4[4], bl4[4];
                LDSM4(bh4[0], bh4[1], bh4[2], bh4[3], bBh + boff[nfp] + kadd);
                LDSM4(bl4[0], bl4[1], bl4[2], bl4[3], bBl + boff[nfp] + kadd);
#pragma unroll
                for (int mf = 0; mf < 2; mf++)
#pragma unroll
                    for (int sub = 0; sub < 2; sub++) {
                        int nf = nfp * 2 + sub;
                        MMA16816(acc[mf][nf], ah[mf], bh4 + 2 * sub);
                        MMA16816(acc[mf][nf], ah[mf], bl4 + 2 * sub);
                        MMA16816(acc[mf][nf], al[mf], bh4 + 2 * sub);
                    }
            }
        }
        __syncthreads();
    }
#undef GISSUE

    if (mode == 0) {
#pragma unroll
        for (int mf = 0; mf < 2; mf++) {
            int r0 = m0 + wm * 32 + mf * 16 + (lane >> 2);
#pragma unroll
            for (int nf = 0; nf < 8; nf++) {
                int col = n0 + wn * 64 + nf * 8 + 2 * (lane & 3);
                if (col < Nn) {
                    float b0 = bias ? bias[col] : 0.f;
                    float b1 = bias ? bias[col + 1] : 0.f;
                    *(float2*)(Cm + (size_t)r0 * Nn + col) =
                        make_float2(acc[mf][nf][0] + b0, acc[mf][nf][1] + b1);
                    *(float2*)(Cm + (size_t)(r0 + 8) * Nn + col) =
                        make_float2(acc[mf][nf][2] + b0, acc[mf][nf][3] + b1);
                }
            }
        }
    } else {
#pragma unroll
        for (int mf = 0; mf < 2; mf++) {
            int r0 = m0 + wm * 32 + mf * 16 + (lane >> 2);
#pragma unroll
            for (int nf = 0; nf < 8; nf++) {
                int col = n0 + wn * 64 + nf * 8 + 2 * (lane & 3);
                if (col < QC) {
                    int s = (col >= 1088) ? 2 : (col >= 544 ? 1 : 0);
                    int rem = col - s * 544;
                    int hh = rem / 68;
                    int d = rem - hh * 68;
                    __nv_bfloat16* Dh = (s == 0) ? g_qh : (s == 1) ? g_kh : g_vh;
                    __nv_bfloat16* Dl = (s == 0) ? g_ql : (s == 1) ? g_kl : g_vl;
#pragma unroll
                    for (int rr = 0; rr < 2; rr++) {
                        int row = r0 + rr * 8;
                        int bb = row >> 10, nn = row & 1023;
                        size_t ad = ((size_t)(bb * HH + hh) * NN + nn) * DP + d;
                        uint32_t hp, lp;
                        packsplit(&hp, &lp, acc[mf][nf][rr * 2], acc[mf][nf][rr * 2 + 1]);
                        *(uint32_t*)(Dh + ad) = hp;
                        *(uint32_t*)(Dl + ad) = lp;
                    }
                }
            }
        }
    }
}

// ---------------------------------------------------------------------------
// Flash attention, mma.sync bf16 split, cp.async double-buffered K/V tiles.
// V loaded from [keys][DP] layout via ldmatrix.trans (no pre-transpose).
// ---------------------------------------------------------------------------
#define AQT 128
#define AKT 64
#define KSTR 88
#define A_KL (AKT * KSTR)
#define A_VH (2 * AKT * KSTR)
#define A_VL (3 * AKT * KSTR)
#define ASTG_H (4 * AKT * KSTR)          // 22528 halves
#define ATTN_SMEM (2 * ASTG_H * 2)       // 90112 bytes

__global__ void __launch_bounds__(256) k_attn_mma(const float* __restrict__ sf_ptr) {
    extern __shared__ __nv_bfloat16 adyn[];
    __shared__ float psc[2][AKT];

    int tid = threadIdx.x, lane = tid & 31, warp = tid >> 5;
    int b = blockIdx.z, h = blockIdx.y, q0 = blockIdx.x * AQT;
    int bh = b * HH + h;
    uint32_t abase = smem_u32(adyn);

    const float sf = sf_ptr[0];
    const float scl = rsqrtf((float)HD);

    uint32_t aoff = (uint32_t)(((warp * 16 + (lane & 15)) * KSTR + 8 * (lane >> 4)) * 2);
    uint32_t boffS[4];
#pragma unroll
    for (int nfp = 0; nfp < 4; nfp++)
        boffS[nfp] = (uint32_t)(((nfp * 16 + (lane & 7) + 8 * (lane >> 4)) * KSTR
                                 + 8 * ((lane >> 3) & 1)) * 2);
    // trans-ldmatrix V address: row = key (lane&15), col = d-group + (lane>>4)*8
    uint32_t vrow = (uint32_t)((((lane & 15) * KSTR) + (lane >> 4) * 8) * 2);

    // ---- stage Q hi then lo through smem, extract A-frags ----
    uint32_t qh[5][4], ql[5][4];
    {
        const __nv_bfloat16* Qg = g_qh + ((size_t)bh * NN + q0) * DP;
        for (int idx = tid; idx < AQT * 10; idx += 256) {
            int r = idx / 10, c = idx - r * 10;
            *(uint4*)(adyn + r * KSTR + c * 8) = *(const uint4*)(Qg + r * DP + c * 8);
        }
        __syncthreads();
#pragma unroll
        for (int kc = 0; kc < 5; kc++)
            LDSM4(qh[kc][0], qh[kc][1], qh[kc][2], qh[kc][3], abase + aoff + kc * 32);
        __syncthreads();
        const __nv_bfloat16* Qg2 = g_ql + ((size_t)bh * NN + q0) * DP;
        for (int idx = tid; idx < AQT * 10; idx += 256) {
            int r = idx / 10, c = idx - r * 10;
            *(uint4*)(adyn + r * KSTR + c * 8) = *(const uint4*)(Qg2 + r * DP + c * 8);
        }
        __syncthreads();
#pragma unroll
        for (int kc = 0; kc < 5; kc++)
            LDSM4(ql[kc][0], ql[kc][1], ql[kc][2], ql[kc][3], abase + aoff + kc * 32);
        __syncthreads();
    }

    float accO[10][4];
#pragma unroll
    for (int i = 0; i < 10; i++)
#pragma unroll
        for (int r = 0; r < 4; r++) accO[i][r] = 0.f;
    float mr0 = -1e30f, mr1 = -1e30f, lr0 = 0.f, lr1 = 0.f;

#define AISSUE(kt_, st) do { \
    uint32_t sb_ = abase + (uint32_t)((st) * ASTG_H * 2); \
    for (int idx = tid; idx < AKT * 10; idx += 256) { \
        int r_ = idx / 10, c_ = idx - r_ * 10; \
        size_t go_ = ((size_t)bh * NN + (kt_) + r_) * DP + c_ * 8; \
        uint32_t do_ = (uint32_t)((r_ * KSTR + c_ * 8) * 2); \
        CP16(sb_ + do_, gptr(g_kh + go_)); \
        CP16(sb_ + (uint32_t)(A_KL * 2) + do_, gptr(g_kl + go_)); \
        CP16(sb_ + (uint32_t)(A_VH * 2) + do_, gptr(g_vh + go_)); \
        CP16(sb_ + (uint32_t)(A_VL * 2) + do_, gptr(g_vl + go_)); \
    } \
    if (tid < AKT) { \
        float pos_ = (float)((kt_) + tid) * (1.0f / (NN - 1)); \
        float dd_ = pos_ - 0.5f; \
        psc[st][tid] = scl * __expf(-sf * dd_ * dd_); \
    } \
} while (0)

    AISSUE(0, 0);
    CPCOMMIT();

    for (int t = 0; t < 16; t++) {
        if (t < 15) {
            AISSUE((t + 1) * AKT, (t + 1) & 1);
            CPCOMMIT();
            CPWAIT1();
        } else {
            CPWAIT0();
        }
        __syncthreads();

        int st = t & 1;
        uint32_t sb = abase + (uint32_t)(st * ASTG_H * 2);
        uint32_t bK0 = sb, bK1 = sb + A_KL * 2;
        uint32_t bV0 = sb + A_VH * 2, bV1 = sb + A_VL * 2;

        // ---- S = Q K^T, 3-pass split ----
        float sacc[8][4];
#pragma unroll
        for (int i = 0; i < 8; i++)
#pragma unroll
            for (int r = 0; r < 4; r++) sacc[i][r] = 0.f;
#pragma unroll
        for (int kc = 0; kc < 5; kc++) {
            uint32_t kadd = kc * 32;
#pragma unroll
            for (int nfp = 0; nfp < 4; nfp++) {
                uint32_t kbh[4], kbl[4];
                LDSM4(kbh[0], kbh[1], kbh[2], kbh[3], bK0 + boffS[nfp] + kadd);
                LDSM4(kbl[0], kbl[1], kbl[2], kbl[3], bK1 + boffS[nfp] + kadd);
#pragma unroll
                for (int sub = 0; sub < 2; sub++) {
                    int nf = nfp * 2 + sub;
                    MMA16816(sacc[nf], qh[kc], kbh + 2 * sub);
                    MMA16816(sacc[nf], qh[kc], kbl + 2 * sub);
                    MMA16816(sacc[nf], ql[kc], kbh + 2 * sub);
                }
            }
        }

        // ---- pos-scale + online softmax ----
        float tm0 = -1e30f, tm1 = -1e30f;
#pragma unroll
        for (int nf = 0; nf < 8; nf++) {
            int c0 = nf * 8 + 2 * (lane & 3);
            float p0 = psc[st][c0], p1 = psc[st][c0 + 1];
            sacc[nf][0] *= p0; sacc[nf][1] *= p1;
            sacc[nf][2] *= p0; sacc[nf][3] *= p1;
            tm0 = fmaxf(tm0, fmaxf(sacc[nf][0], sacc[nf][1]));
            tm1 = fmaxf(tm1, fmaxf(sacc[nf][2], sacc[nf][3]));
        }
        tm0 = fmaxf(tm0, __shfl_xor_sync(0xffffffffu, tm0, 1));
        tm0 = fmaxf(tm0, __shfl_xor_sync(0xffffffffu, tm0, 2));
        tm1 = fmaxf(tm1, __shfl_xor_sync(0xffffffffu, tm1, 1));
        tm1 = fmaxf(tm1, __shfl_xor_sync(0xffffffffu, tm1, 2));
        float mn0 = fmaxf(mr0, tm0), mn1 = fmaxf(mr1, tm1);
        float corr0 = __expf(mr0 - mn0), corr1 = __expf(mr1 - mn1);
        float s0 = 0.f, s1 = 0.f;
#pragma unroll
        for (int nf = 0; nf < 8; nf++) {
            sacc[nf][0] = __expf(sacc[nf][0] - mn0);
            sacc[nf][1] = __expf(sacc[nf][1] - mn0);
            sacc[nf][2] = __expf(sacc[nf][2] - mn1);
            sacc[nf][3] = __expf(sacc[nf][3] - mn1);
            s0 += sacc[nf][0] + sacc[nf][1];
            s1 += sacc[nf][2] + sacc[nf][3];
        }
        s0 += __shfl_xor_sync(0xffffffffu, s0, 1);
        s0 += __shfl_xor_sync(0xffffffffu, s0, 2);
        s1 += __shfl_xor_sync(0xffffffffu, s1, 1);
        s1 += __shfl_xor_sync(0xffffffffu, s1, 2);
        lr0 = lr0 * corr0 + s0;
        lr1 = lr1 * corr1 + s1;
        mr0 = mn0; mr1 = mn1;
#pragma unroll
        for (int nf = 0; nf < 10; nf++) {
            accO[nf][0] *= corr0; accO[nf][1] *= corr0;
            accO[nf][2] *= corr1; accO[nf][3] *= corr1;
        }

        // ---- pack P into A-frags (hi/lo) ----
        uint32_t pAh[4][4], pAl[4][4];
#pragma unroll
        for (int g = 0; g < 4; g++) {
            packsplit(&pAh[g][0], &pAl[g][0], sacc[2 * g][0], sacc[2 * g][1]);
            packsplit(&pAh[g][1], &pAl[g][1], sacc[2 * g][2], sacc[2 * g][3]);
            packsplit(&pAh[g][2], &pAl[g][2], sacc[2 * g + 1][0], sacc[2 * g + 1][1]);
            packsplit(&pAh[g][3], &pAl[g][3], sacc[2 * g + 1][2], sacc[2 * g + 1][3]);
        }

        // ---- O += P V, 3-pass split (trans-ldmatrix V from [keys][DP]) ----
#pragma unroll
        for (int kk = 0; kk < 4; kk++) {
            uint32_t kadd = (uint32_t)(kk * 16 * KSTR * 2);
#pragma unroll
            for (int nfp = 0; nfp < 5; nfp++) {
                uint32_t voff = vrow + kadd + (uint32_t)(nfp * 16 * 2);
                uint32_t vbh[4], vbl[4];
                LDSM4T(vbh[0], vbh[1], vbh[2], vbh[3], bV0 + voff);
                LDSM4T(vbl[0], vbl[1], vbl[2], vbl[3], bV1 + voff);
#pragma unroll
                for (int sub = 0; sub < 2; sub++) {
                    int nf = nfp * 2 + sub;
                    MMA16816(accO[nf], pAh[kk], vbh + 2 * sub);
                    MMA16816(accO[nf], pAh[kk], vbl + 2 * sub);
                    MMA16816(accO[nf], pAl[kk], vbh + 2 * sub);
                }
            }
        }
        __syncthreads();
    }
#undef AISSUE

    // ---- epilogue: normalize, store bf16 hi/lo into proj-A buffers ----
    float inv0 = 1.0f / lr0, inv1 = 1.0f / lr1;
    int r = lane >> 2;
    int n_0 = q0 + warp * 16 + r;
#pragma unroll
    for (int nf = 0; nf < 10; nf++) {
        int d0 = nf * 8 + 2 * (lane & 3);
        if (d0 + 1 < HD) {
            size_t a0 = ((size_t)(b * NN + n_0)) * CC + h * HD + d0;
            size_t a1 = ((size_t)(b * NN + n_0 + 8)) * CC + h * HD + d0;
            uint32_t hp, lp;
            packsplit(&hp, &lp, accO[nf][0] * inv0, accO[nf][1] * inv0);
            *(uint32_t*)(g_ah + a0) = hp;
            *(uint32_t*)(g_al + a0) = lp;
            packsplit(&hp, &lp, accO[nf][2] * inv1, accO[nf][3] * inv1);
            *(uint32_t*)(g_ah + a1) = hp;
            *(uint32_t*)(g_al + a1) = lp;
        }
    }
}

// ---------------------------------------------------------------------------
extern "C" void kernel_launch(void* const* d_in, const int* in_sizes, int n_in,
                              void* d_out, int out_size) {
    const float* x       = (const float*)d_in[0];
    const float* norm_g  = (const float*)d_in[1];
    const float* norm_b  = (const float*)d_in[2];
    const float* ap_w    = (const float*)d_in[3];
    const float* ap_b    = (const float*)d_in[4];
    const float* norm2_g = (const float*)d_in[5];
    const float* norm2_b = (const float*)d_in[6];
    const float* qkv_w   = (const float*)d_in[7];
    const float* proj_w  = (const float*)d_in[8];
    const float* proj_b  = (const float*)d_in[9];
    const float* scaling = (const float*)d_in[10];
    float* out = (float*)d_out;

    static int attr_set = 0;
    if (!attr_set) {
        cudaFuncSetAttribute(k_mma_gemm, cudaFuncAttributeMaxDynamicSharedMemorySize, GEMM_SMEM);
        cudaFuncSetAttribute(k_attn_mma, cudaFuncAttributeMaxDynamicSharedMemorySize, ATTN_SMEM);
        attr_set = 1;
    }

    __nv_bfloat16 *p_qbh, *p_qbl, *p_pbh, *p_pbl, *p_ah, *p_al;
    cudaGetSymbolAddress((void**)&p_qbh, g_qbh);
    cudaGetSymbolAddress((void**)&p_qbl, g_qbl);
    cudaGetSymbolAddress((void**)&p_pbh, g_pbh);
    cudaGetSymbolAddress((void**)&p_pbl, g_pbl);
    cudaGetSymbolAddress((void**)&p_ah, g_ah);
    cudaGetSymbolAddress((void**)&p_al, g_al);

    // launch #1: fused preprocessing (scores + both weight converts + pads)
    k_pre<<<PRE_PAD, CC>>>(x, norm_g, norm_b, ap_w, ap_b, qkv_w, proj_w);
    // launch #2
    k_softmax_seq<<<Bb * JJ, 256>>>();
    // launch #3
    k_pool_ln<<<Bb * NN, CC>>>(x, norm_g, norm_b, norm2_g, norm2_b);
    // launch #4 (profiled by ncu): QKV GEMM
    k_mma_gemm<<<dim3(13, (Bb * NN) / GBM), 256, GEMM_SMEM>>>(
        p_ah, p_al, p_qbh, p_qbl, nullptr, QC, nullptr, 1);
    // launch #5: attention
    k_attn_mma<<<dim3(NN / AQT, HH, Bb), 256, ATTN_SMEM>>>(scaling);
    // launch #6: proj GEMM
    k_mma_gemm<<<dim3(5, (Bb * NN) / GBM), 256, GEMM_SMEM>>>(
        p_ah, p_al, p_pbh, p_pbl, out, CC, proj_b, 0);
}

// round 8
// speedup vs baseline: 3.9673x; 1.3337x over previous
#include <cuda_runtime.h>
#include <cuda_fp16.h>
#include <math.h>
#include <stdint.h>

typedef unsigned long long ull;

#define Bb 8
#define NN 1024
#define CC 544
#define JJ 17
#define FF 32
#define HH 8
#define HD 68
#define QC 1632
#define DP 80     // padded head dim

// tensor-core warp ops (family-common PTX, OK on plain sm_103 target)
#define LDSM4(r0,r1,r2,r3,addr) \
    asm volatile("ldmatrix.sync.aligned.m8n8.x4.shared.b16 {%0,%1,%2,%3}, [%4];" \
        : "=r"(r0),"=r"(r1),"=r"(r2),"=r"(r3) : "r"(addr))
#define LDSM4T(r0,r1,r2,r3,addr) \
    asm volatile("ldmatrix.sync.aligned.m8n8.x4.trans.shared.b16 {%0,%1,%2,%3}, [%4];" \
        : "=r"(r0),"=r"(r1),"=r"(r2),"=r"(r3) : "r"(addr))
#define MMAH(d,a,b) \
    asm volatile("mma.sync.aligned.m16n8k16.row.col.f32.f16.f16.f32 " \
        "{%0,%1,%2,%3}, {%4,%5,%6,%7}, {%8,%9}, {%0,%1,%2,%3};" \
        : "+f"((d)[0]),"+f"((d)[1]),"+f"((d)[2]),"+f"((d)[3]) \
        : "r"((a)[0]),"r"((a)[1]),"r"((a)[2]),"r"((a)[3]), "r"((b)[0]),"r"((b)[1]))

#define CP16(dst, src) \
    asm volatile("cp.async.cg.shared.global [%0], [%1], 16;" \
        :: "r"(dst), "l"(src) : "memory")
#define CP16Z(dst, src, sz) \
    asm volatile("cp.async.cg.shared.global [%0], [%1], 16, %2;" \
        :: "r"(dst), "l"(src), "r"(sz) : "memory")
#define CPCOMMIT() asm volatile("cp.async.commit_group;" ::: "memory")
#define CPWAIT1()  asm volatile("cp.async.wait_group 1;" ::: "memory")
#define CPWAIT0()  asm volatile("cp.async.wait_group 0;" ::: "memory")

__device__ __forceinline__ uint32_t smem_u32(const void* p) {
    uint32_t a;
    asm("{ .reg .u64 t; cvta.to.shared.u64 t, %1; cvt.u32.u64 %0, t; }" : "=r"(a) : "l"(p));
    return a;
}
__device__ __forceinline__ const void* gptr(const void* p) {
    return (const void*)__cvta_generic_to_global(p);
}
// fp16 hi/lo split of a float pair, packed as half2 words
__device__ __forceinline__ void packsplit_h(uint32_t* hp, uint32_t* lp, float v0, float v1) {
    __half2 h = __floats2half2_rn(v0, v1);
    float2 hf = __half22float2(h);
    __half2 l = __floats2half2_rn(v0 - hf.x, v1 - hf.y);
    *hp = *(uint32_t*)&h;
    *lp = *(uint32_t*)&l;
}
__device__ __forceinline__ uint32_t packh2(float v0, float v1) {
    __half2 h = __floats2half2_rn(v0, v1);
    return *(uint32_t*)&h;
}

// -------- scratch --------
__device__ float g_sc [(size_t)Bb * NN * JJ];
__device__ float g_w  [(size_t)Bb * NN * JJ];
__device__ __half g_ah [(size_t)Bb * NN * CC];   // A hi (xp, then attn-out)
__device__ __half g_al [(size_t)Bb * NN * CC];   // A lo
__device__ __half g_qb [(size_t)QC * CC];        // qkv weights fp16
__device__ __half g_pb [(size_t)CC * CC];        // proj weights fp16
__device__ __half g_qh [(size_t)Bb * HH * NN * DP];
__device__ __half g_ql [(size_t)Bb * HH * NN * DP];
__device__ __half g_kh [(size_t)Bb * HH * NN * DP];
__device__ __half g_vh [(size_t)Bb * HH * NN * DP];

__device__ __forceinline__ float wsum(float v) {
#pragma unroll
    for (int o = 16; o > 0; o >>= 1) v += __shfl_xor_sync(0xffffffffu, v, o);
    return v;
}
__device__ __forceinline__ float wmax(float v) {
#pragma unroll
    for (int o = 16; o > 0; o >>= 1) v = fmaxf(v, __shfl_xor_sync(0xffffffffu, v, o));
    return v;
}

// ---------------------------------------------------------------------------
// Kernel 1 (fused preprocessing): scores + weight fp16 converts + pad zeroing
// ---------------------------------------------------------------------------
#define PRE_SCORE 8192
#define PRE_CVTQ  (PRE_SCORE + 408)
#define PRE_CVTP  (PRE_CVTQ + 136)
#define PRE_PAD   (PRE_CVTP + 1446)

__global__ void k_pre(const float* __restrict__ x,
                      const float* __restrict__ ng,
                      const float* __restrict__ nb,
                      const float* __restrict__ apw,
                      const float* __restrict__ apb,
                      const float* __restrict__ qkv_w,
                      const float* __restrict__ proj_w) {
    int blk = blockIdx.x;
    int tid = threadIdx.x;
    if (blk < PRE_SCORE) {
        int bn = blk;
        int j = tid >> 5, f = tid & 31;
        float v = x[(size_t)bn * CC + j * FF + f];
        float mu = wsum(v) * (1.0f / FF);
        float d = v - mu;
        float var = wsum(d * d) * (1.0f / FF);
        float xn = d * rsqrtf(var + 1e-5f) * ng[f] + nb[f];
        float sc = wsum(xn * apw[f]);
        if (f == 0) g_sc[(size_t)bn * JJ + j] = sc + apb[0];
    } else if (blk < PRE_CVTQ) {
        int idx = (blk - PRE_SCORE) * 544 + tid;    // < 221952 exactly
        float4 v = ((const float4*)qkv_w)[idx];
        ((uint2*)g_qb)[idx] = make_uint2(packh2(v.x, v.y), packh2(v.z, v.w));
    } else if (blk < PRE_CVTP) {
        int idx = (blk - PRE_CVTQ) * 544 + tid;     // < 73984 exactly
        float4 v = ((const float4*)proj_w)[idx];
        ((uint2*)g_pb)[idx] = make_uint2(packh2(v.x, v.y), packh2(v.z, v.w));
    } else {
        int idx = (blk - PRE_CVTP) * 544 + tid;
        if (idx < 64 * 1024 * (DP - HD)) {
            int bhn = idx / (DP - HD), d = HD + (idx - bhn * (DP - HD));
            size_t ad = (size_t)bhn * DP + d;
            __half z = __float2half(0.f);
            g_qh[ad] = z; g_ql[ad] = z; g_kh[ad] = z;
        }
    }
}

// ---------------------------------------------------------------------------
// Kernel 2: softmax over sequence axis N per (b, joint)
// ---------------------------------------------------------------------------
__global__ void k_softmax_seq() {
    int bj = blockIdx.x;
    int b = bj / JJ, j = bj - b * JJ;
    int tid = threadIdx.x;
    const float* base = g_sc + (size_t)b * NN * JJ + j;

    float v[4];
#pragma unroll
    for (int i = 0; i < 4; i++) v[i] = base[(size_t)(tid + i * 256) * JJ];

    __shared__ float red[8];
    __shared__ float bc;
    int wid = tid >> 5, lane = tid & 31;

    float mx = fmaxf(fmaxf(v[0], v[1]), fmaxf(v[2], v[3]));
    mx = wmax(mx);
    if (lane == 0) red[wid] = mx;
    __syncthreads();
    if (tid == 0) {
        float m = red[0];
        for (int i = 1; i < 8; i++) m = fmaxf(m, red[i]);
        bc = m;
    }
    __syncthreads();
    mx = bc;
    __syncthreads();

    float se = 0.f;
#pragma unroll
    for (int i = 0; i < 4; i++) { v[i] = __expf(v[i] - mx); se += v[i]; }
    se = wsum(se);
    if (lane == 0) red[wid] = se;
    __syncthreads();
    if (tid == 0) {
        float s = 0.f;
        for (int i = 0; i < 8; i++) s += red[i];
        bc = 1.0f / s;
    }
    __syncthreads();
    float inv = bc;

    float* wbase = g_w + (size_t)b * NN * JJ + j;
#pragma unroll
    for (int i = 0; i < 4; i++) wbase[(size_t)(tid + i * 256) * JJ] = v[i] * inv;
}

// ---------------------------------------------------------------------------
// Kernel 3: recompute joint-LN from x, pool, LN over C -> fp16 hi/lo
// ---------------------------------------------------------------------------
__global__ void k_pool_ln(const float* __restrict__ x,
                          const float* __restrict__ ng,
                          const float* __restrict__ nb,
                          const float* __restrict__ g2,
                          const float* __restrict__ b2) {
    int bn = blockIdx.x;
    int c = threadIdx.x;
    int wid = c >> 5, lane = c & 31;
    __shared__ float red[17];
    __shared__ float bc0, bc1;

    float xv = x[(size_t)bn * CC + c];
    float mu_j = wsum(xv) * (1.0f / FF);
    float dj = xv - mu_j;
    float var_j = wsum(dj * dj) * (1.0f / FF);
    float xn = dj * rsqrtf(var_j + 1e-5f) * ng[lane] + nb[lane];

    float v = xn * g_w[(size_t)bn * JJ + wid];

    float s = wsum(v);
    if (lane == 0) red[wid] = s;
    __syncthreads();
    if (wid == 0) {
        float t = (lane < 17) ? red[lane] : 0.f;
        t = wsum(t);
        if (lane == 0) bc0 = t * (1.0f / CC);
    }
    __syncthreads();
    float mu = bc0;
    float d = v - mu;

    float s2 = wsum(d * d);
    if (lane == 0) red[wid] = s2;
    __syncthreads();
    if (wid == 0) {
        float t = (lane < 17) ? red[lane] : 0.f;
        t = wsum(t);
        if (lane == 0) bc1 = t * (1.0f / CC);
    }
    __syncthreads();
    float var = bc1;

    float xp = d * rsqrtf(var + 1e-5f) * g2[c] + b2[c];
    __half h = __float2half_rn(xp);
    __half l = __float2half_rn(xp - __half2float(h));
    size_t o = (size_t)bn * CC + c;
    g_ah[o] = h; g_al[o] = l;
}

// ---------------------------------------------------------------------------
// cp.async double-buffered mma.sync fp16 2-pass GEMM.
// A split hi/lo, B single fp16. mode 0: fp32 C (+bias). mode 1: scatter QKV.
// ---------------------------------------------------------------------------
#define GBM 128
#define GBN 128
#define GBK 32
#define SST 40
#define CH_H (GBM * SST)            // 5120 halves per sub-array
#define STG_H (3 * CH_H)            // Ah, Al, Bh
#define GEMM_SMEM (2 * STG_H * 2)   // 61440 B

__global__ void __launch_bounds__(256) k_mma_gemm(
        const __half* __restrict__ Ah, const __half* __restrict__ Al,
        const __half* __restrict__ Bh,
        float* __restrict__ Cm, int Nn, const float* __restrict__ bias, int mode) {
    extern __shared__ __half dyn[];
    int tid = threadIdx.x;
    int lane = tid & 31, warp = tid >> 5;
    int wm = warp >> 1, wn = warp & 1;
    int m0 = blockIdx.y * GBM, n0 = blockIdx.x * GBN;
    uint32_t base = smem_u32(dyn);

    float acc[2][8][4];
#pragma unroll
    for (int i = 0; i < 2; i++)
#pragma unroll
        for (int j = 0; j < 8; j++)
#pragma unroll
            for (int r = 0; r < 4; r++) acc[i][j][r] = 0.f;

    uint32_t aoff[2];
#pragma unroll
    for (int mf = 0; mf < 2; mf++)
        aoff[mf] = (uint32_t)(((wm * 32 + mf * 16 + (lane & 15)) * SST + 8 * (lane >> 4)) * 2);
    uint32_t boff[4];
#pragma unroll
    for (int nfp = 0; nfp < 4; nfp++)
        boff[nfp] = (uint32_t)(((wn * 64 + nfp * 16 + (lane & 7) + 8 * (lane >> 4)) * SST
                                + 8 * ((lane >> 3) & 1)) * 2);

    int lrow = tid >> 2;
    int lc = (tid & 3) * 8;

#define GISSUE(ck, st) do { \
    int kb_ = (ck) * GBK; \
    uint32_t sb_ = base + (uint32_t)((st) * STG_H * 2); \
    _Pragma("unroll") \
    for (int half_ = 0; half_ < 2; half_++) { \
        int row_ = lrow + half_ * 64; \
        uint32_t do_ = (uint32_t)((row_ * SST + lc) * 2); \
        CP16(sb_ + do_, gptr(Ah + (size_t)(m0 + row_) * CC + kb_ + lc)); \
        CP16(sb_ + (uint32_t)(CH_H * 2) + do_, gptr(Al + (size_t)(m0 + row_) * CC + kb_ + lc)); \
        int ok_ = (n0 + row_ < Nn) ? 16 : 0; \
        int br_ = (n0 + row_ < Nn) ? row_ : 0; \
        CP16Z(sb_ + (uint32_t)(2 * CH_H * 2) + do_, gptr(Bh + (size_t)(n0 + br_) * CC + kb_ + lc), ok_); \
    } \
} while (0)

    GISSUE(0, 0);
    CPCOMMIT();

    for (int ck = 0; ck < 17; ck++) {
        if (ck < 16) {
            GISSUE(ck + 1, (ck + 1) & 1);
            CPCOMMIT();
            CPWAIT1();
        } else {
            CPWAIT0();
        }
        __syncthreads();

        uint32_t sb = base + (uint32_t)((ck & 1) * STG_H * 2);
        uint32_t bAh = sb, bAl = sb + CH_H * 2;
        uint32_t bBh = sb + 2 * CH_H * 2;
#pragma unroll
        for (int ks = 0; ks < 2; ks++) {
            uint32_t kadd = (uint32_t)(ks * 16 * 2);
            uint32_t ah[2][4], al[2][4];
#pragma unroll
            for (int mf = 0; mf < 2; mf++) {
                LDSM4(ah[mf][0], ah[mf][1], ah[mf][2], ah[mf][3], bAh + aoff[mf] + kadd);
                LDSM4(al[mf][0], al[mf][1], al[mf][2], al[mf][3], bAl + aoff[mf] + kadd);
            }
#pragma unroll
            for (int nfp = 0; nfp < 4; nfp++) {
                uint32_t bh4[4];
                LDSM4(bh4[0], bh4[1], bh4[2], bh4[3], bBh + boff[nfp] + kadd);
#pragma unroll
                for (int mf = 0; mf < 2; mf++)
#pragma unroll
                    for (int sub = 0; sub < 2; sub++) {
                        int nf = nfp * 2 + sub;
                        MMAH(acc[mf][nf], ah[mf], bh4 + 2 * sub);
                        MMAH(acc[mf][nf], al[mf], bh4 + 2 * sub);
                    }
            }
        }
        __syncthreads();
    }
#undef GISSUE

    if (mode == 0) {
#pragma unroll
        for (int mf = 0; mf < 2; mf++) {
            int r0 = m0 + wm * 32 + mf * 16 + (lane >> 2);
#pragma unroll
            for (int nf = 0; nf < 8; nf++) {
                int col = n0 + wn * 64 + nf * 8 + 2 * (lane & 3);
                if (col < Nn) {
                    float b0 = bias ? bias[col] : 0.f;
                    float b1 = bias ? bias[col + 1] : 0.f;
                    *(float2*)(Cm + (size_t)r0 * Nn + col) =
                        make_float2(acc[mf][nf][0] + b0, acc[mf][nf][1] + b1);
                    *(float2*)(Cm + (size_t)(r0 + 8) * Nn + col) =
                        make_float2(acc[mf][nf][2] + b0, acc[mf][nf][3] + b1);
                }
            }
        }
    } else {
        // scatter: Q -> hi/lo split; K,V -> single fp16. layout [bh][n][DP]
#pragma unroll
        for (int mf = 0; mf < 2; mf++) {
            int r0 = m0 + wm * 32 + mf * 16 + (lane >> 2);
#pragma unroll
            for (int nf = 0; nf < 8; nf++) {
                int col = n0 + wn * 64 + nf * 8 + 2 * (lane & 3);
                if (col < QC) {
                    int s = (col >= 1088) ? 2 : (col >= 544 ? 1 : 0);
                    int rem = col - s * 544;
                    int hh = rem / 68;
                    int d = rem - hh * 68;
#pragma unroll
                    for (int rr = 0; rr < 2; rr++) {
                        int row = r0 + rr * 8;
                        int bb = row >> 10, nn = row & 1023;
                        size_t ad = ((size_t)(bb * HH + hh) * NN + nn) * DP + d;
                        float a0 = acc[mf][nf][rr * 2], a1 = acc[mf][nf][rr * 2 + 1];
                        if (s == 0) {
                            uint32_t hp, lp;
                            packsplit_h(&hp, &lp, a0, a1);
                            *(uint32_t*)(g_qh + ad) = hp;
                            *(uint32_t*)(g_ql + ad) = lp;
                        } else {
                            __half* D = (s == 1) ? g_kh : g_vh;
                            *(uint32_t*)(D + ad) = packh2(a0, a1);
                        }
                    }
                }
            }
        }
    }
}

// ---------------------------------------------------------------------------
// Flash attention, mma.sync fp16 2-pass, cp.async double-buffered K/V tiles.
// K,V single fp16; Q and P split hi/lo. V via ldmatrix.trans.
// ---------------------------------------------------------------------------
#define AQT 128
#define AKT 64
#define KSTR 88
#define A_VH (AKT * KSTR)                // 5632
#define ASTG_H (2 * AKT * KSTR)          // 11264 halves
#define ATTN_SMEM (2 * ASTG_H * 2)       // 45056 bytes

__global__ void __launch_bounds__(256) k_attn_mma(const float* __restrict__ sf_ptr) {
    extern __shared__ __half adyn[];
    __shared__ float psc[2][AKT];

    int tid = threadIdx.x, lane = tid & 31, warp = tid >> 5;
    int b = blockIdx.z, h = blockIdx.y, q0 = blockIdx.x * AQT;
    int bh = b * HH + h;
    uint32_t abase = smem_u32(adyn);

    const float sf = sf_ptr[0];
    const float scl = rsqrtf((float)HD);

    uint32_t aoff = (uint32_t)(((warp * 16 + (lane & 15)) * KSTR + 8 * (lane >> 4)) * 2);
    uint32_t boffS[4];
#pragma unroll
    for (int nfp = 0; nfp < 4; nfp++)
        boffS[nfp] = (uint32_t)(((nfp * 16 + (lane & 7) + 8 * (lane >> 4)) * KSTR
                                 + 8 * ((lane >> 3) & 1)) * 2);
    uint32_t vrow = (uint32_t)((((lane & 15) * KSTR) + (lane >> 4) * 8) * 2);

    // ---- stage Q hi then lo through smem, extract A-frags ----
    uint32_t qh[5][4], ql[5][4];
    {
        const __half* Qg = g_qh + ((size_t)bh * NN + q0) * DP;
        for (int idx = tid; idx < AQT * 10; idx += 256) {
            int r = idx / 10, c = idx - r * 10;
            *(uint4*)(adyn + r * KSTR + c * 8) = *(const uint4*)(Qg + r * DP + c * 8);
        }
        __syncthreads();
#pragma unroll
        for (int kc = 0; kc < 5; kc++)
            LDSM4(qh[kc][0], qh[kc][1], qh[kc][2], qh[kc][3], abase + aoff + kc * 32);
        __syncthreads();
        const __half* Qg2 = g_ql + ((size_t)bh * NN + q0) * DP;
        for (int idx = tid; idx < AQT * 10; idx += 256) {
            int r = idx / 10, c = idx - r * 10;
            *(uint4*)(adyn + r * KSTR + c * 8) = *(const uint4*)(Qg2 + r * DP + c * 8);
        }
        __syncthreads();
#pragma unroll
        for (int kc = 0; kc < 5; kc++)
            LDSM4(ql[kc][0], ql[kc][1], ql[kc][2], ql[kc][3], abase + aoff + kc * 32);
        __syncthreads();
    }

    float accO[10][4];
#pragma unroll
    for (int i = 0; i < 10; i++)
#pragma unroll
        for (int r = 0; r < 4; r++) accO[i][r] = 0.f;
    float mr0 = -1e30f, mr1 = -1e30f, lr0 = 0.f, lr1 = 0.f;

#define AISSUE(kt_, st) do { \
    uint32_t sb_ = abase + (uint32_t)((st) * ASTG_H * 2); \
    for (int idx = tid; idx < AKT * 10; idx += 256) { \
        int r_ = idx / 10, c_ = idx - r_ * 10; \
        size_t go_ = ((size_t)bh * NN + (kt_) + r_) * DP + c_ * 8; \
        uint32_t do_ = (uint32_t)((r_ * KSTR + c_ * 8) * 2); \
        CP16(sb_ + do_, gptr(g_kh + go_)); \
        CP16(sb_ + (uint32_t)(A_VH * 2) + do_, gptr(g_vh + go_)); \
    } \
    if (tid < AKT) { \
        float pos_ = (float)((kt_) + tid) * (1.0f / (NN - 1)); \
        float dd_ = pos_ - 0.5f; \
        psc[st][tid] = scl * __expf(-sf * dd_ * dd_); \
    } \
} while (0)

    AISSUE(0, 0);
    CPCOMMIT();

    for (int t = 0; t < 16; t++) {
        if (t < 15) {
            AISSUE((t + 1) * AKT, (t + 1) & 1);
            CPCOMMIT();
            CPWAIT1();
        } else {
            CPWAIT0();
        }
        __syncthreads();

        int st = t & 1;
        uint32_t sb = abase + (uint32_t)(st * ASTG_H * 2);
        uint32_t bK0 = sb;
        uint32_t bV0 = sb + A_VH * 2;

        // ---- S = Q K^T, fp16 2-pass ----
        float sacc[8][4];
#pragma unroll
        for (int i = 0; i < 8; i++)
#pragma unroll
            for (int r = 0; r < 4; r++) sacc[i][r] = 0.f;
#pragma unroll
        for (int kc = 0; kc < 5; kc++) {
            uint32_t kadd = kc * 32;
#pragma unroll
            for (int nfp = 0; nfp < 4; nfp++) {
                uint32_t kbh[4];
                LDSM4(kbh[0], kbh[1], kbh[2], kbh[3], bK0 + boffS[nfp] + kadd);
#pragma unroll
                for (int sub = 0; sub < 2; sub++) {
                    int nf = nfp * 2 + sub;
                    MMAH(sacc[nf], qh[kc], kbh + 2 * sub);
                    MMAH(sacc[nf], ql[kc], kbh + 2 * sub);
                }
            }
        }

        // ---- pos-scale + online softmax ----
        float tm0 = -1e30f, tm1 = -1e30f;
#pragma unroll
        for (int nf = 0; nf < 8; nf++) {
            int c0 = nf * 8 + 2 * (lane & 3);
            float p0 = psc[st][c0], p1 = psc[st][c0 + 1];
            sacc[nf][0] *= p0; sacc[nf][1] *= p1;
            sacc[nf][2] *= p0; sacc[nf][3] *= p1;
            tm0 = fmaxf(tm0, fmaxf(sacc[nf][0], sacc[nf][1]));
            tm1 = fmaxf(tm1, fmaxf(sacc[nf][2], sacc[nf][3]));
        }
        tm0 = fmaxf(tm0, __shfl_xor_sync(0xffffffffu, tm0, 1));
        tm0 = fmaxf(tm0, __shfl_xor_sync(0xffffffffu, tm0, 2));
        tm1 = fmaxf(tm1, __shfl_xor_sync(0xffffffffu, tm1, 1));
        tm1 = fmaxf(tm1, __shfl_xor_sync(0xffffffffu, tm1, 2));
        float mn0 = fmaxf(mr0, tm0), mn1 = fmaxf(mr1, tm1);
        float corr0 = __expf(mr0 - mn0), corr1 = __expf(mr1 - mn1);
        float s0 = 0.f, s1 = 0.f;
#pragma unroll
        for (int nf = 0; nf < 8; nf++) {
            sacc[nf][0] = __expf(sacc[nf][0] - mn0);
            sacc[nf][1] = __expf(sacc[nf][1] - mn0);
            sacc[nf][2] = __expf(sacc[nf][2] - mn1);
            sacc[nf][3] = __expf(sacc[nf][3] - mn1);
            s0 += sacc[nf][0] + sacc[nf][1];
            s1 += sacc[nf][2] + sacc[nf][3];
        }
        s0 += __shfl_xor_sync(0xffffffffu, s0, 1);
        s0 += __shfl_xor_sync(0xffffffffu, s0, 2);
        s1 += __shfl_xor_sync(0xffffffffu, s1, 1);
        s1 += __shfl_xor_sync(0xffffffffu, s1, 2);
        lr0 = lr0 * corr0 + s0;
        lr1 = lr1 * corr1 + s1;
        mr0 = mn0; mr1 = mn1;
#pragma unroll
        for (int nf = 0; nf < 10; nf++) {
            accO[nf][0] *= corr0; accO[nf][1] *= corr0;
            accO[nf][2] *= corr1; accO[nf][3] *= corr1;
        }

        // ---- pack P into A-frags (fp16 hi/lo) ----
        uint32_t pAh[4][4], pAl[4][4];
#pragma unroll
        for (int g = 0; g < 4; g++) {
            packsplit_h(&pAh[g][0], &pAl[g][0], sacc[2 * g][0], sacc[2 * g][1]);
            packsplit_h(&pAh[g][1], &pAl[g][1], sacc[2 * g][2], sacc[2 * g][3]);
            packsplit_h(&pAh[g][2], &pAl[g][2], sacc[2 * g + 1][0], sacc[2 * g + 1][1]);
            packsplit_h(&pAh[g][3], &pAl[g][3], sacc[2 * g + 1][2], sacc[2 * g + 1][3]);
        }

        // ---- O += P V, fp16 2-pass (trans-ldmatrix V from [keys][DP]) ----
#pragma unroll
        for (int kk = 0; kk < 4; kk++) {
            uint32_t kadd = (uint32_t)(kk * 16 * KSTR * 2);
#pragma unroll
            for (int nfp = 0; nfp < 5; nfp++) {
                uint32_t voff = vrow + kadd + (uint32_t)(nfp * 16 * 2);
                uint32_t vbh[4];
                LDSM4T(vbh[0], vbh[1], vbh[2], vbh[3], bV0 + voff);
#pragma unroll
                for (int sub = 0; sub < 2; sub++) {
                    int nf = nfp * 2 + sub;
                    MMAH(accO[nf], pAh[kk], vbh + 2 * sub);
                    MMAH(accO[nf], pAl[kk], vbh + 2 * sub);
                }
            }
        }
        __syncthreads();
    }
#undef AISSUE

    // ---- epilogue: normalize, store fp16 hi/lo into proj-A buffers ----
    float inv0 = 1.0f / lr0, inv1 = 1.0f / lr1;
    int r = lane >> 2;
    int n_0 = q0 + warp * 16 + r;
#pragma unroll
    for (int nf = 0; nf < 10; nf++) {
        int d0 = nf * 8 + 2 * (lane & 3);
        if (d0 + 1 < HD) {
            size_t a0 = ((size_t)(b * NN + n_0)) * CC + h * HD + d0;
            size_t a1 = ((size_t)(b * NN + n_0 + 8)) * CC + h * HD + d0;
            uint32_t hp, lp;
            packsplit_h(&hp, &lp, accO[nf][0] * inv0, accO[nf][1] * inv0);
            *(uint32_t*)(g_ah + a0) = hp;
            *(uint32_t*)(g_al + a0) = lp;
            packsplit_h(&hp, &lp, accO[nf][2] * inv1, accO[nf][3] * inv1);
            *(uint32_t*)(g_ah + a1) = hp;
            *(uint32_t*)(g_al + a1) = lp;
        }
    }
}

// ---------------------------------------------------------------------------
extern "C" void kernel_launch(void* const* d_in, const int* in_sizes, int n_in,
                              void* d_out, int out_size) {
    const float* x       = (const float*)d_in[0];
    const float* norm_g  = (const float*)d_in[1];
    const float* norm_b  = (const float*)d_in[2];
    const float* ap_w    = (const float*)d_in[3];
    const float* ap_b    = (const float*)d_in[4];
    const float* norm2_g = (const float*)d_in[5];
    const float* norm2_b = (const float*)d_in[6];
    const float* qkv_w   = (const float*)d_in[7];
    const float* proj_w  = (const float*)d_in[8];
    const float* proj_b  = (const float*)d_in[9];
    const float* scaling = (const float*)d_in[10];
    float* out = (float*)d_out;

    static int attr_set = 0;
    if (!attr_set) {
        cudaFuncSetAttribute(k_mma_gemm, cudaFuncAttributeMaxDynamicSharedMemorySize, GEMM_SMEM);
        cudaFuncSetAttribute(k_attn_mma, cudaFuncAttributeMaxDynamicSharedMemorySize, ATTN_SMEM);
        attr_set = 1;
    }

    __half *p_qb, *p_pb, *p_ah, *p_al;
    cudaGetSymbolAddress((void**)&p_qb, g_qb);
    cudaGetSymbolAddress((void**)&p_pb, g_pb);
    cudaGetSymbolAddress((void**)&p_ah, g_ah);
    cudaGetSymbolAddress((void**)&p_al, g_al);

    // launch #1: fused preprocessing
    k_pre<<<PRE_PAD, CC>>>(x, norm_g, norm_b, ap_w, ap_b, qkv_w, proj_w);
    // launch #2
    k_softmax_seq<<<Bb * JJ, 256>>>();
    // launch #3
    k_pool_ln<<<Bb * NN, CC>>>(x, norm_g, norm_b, norm2_g, norm2_b);
    // launch #4 (profiled): QKV GEMM
    k_mma_gemm<<<dim3(13, (Bb * NN) / GBM), 256, GEMM_SMEM>>>(
        p_ah, p_al, p_qb, nullptr, QC, nullptr, 1);
    // launch #5: attention
    k_attn_mma<<<dim3(NN / AQT, HH, Bb), 256, ATTN_SMEM>>>(scaling);
    // launch #6: proj GEMM
    k_mma_gemm<<<dim3(5, (Bb * NN) / GBM), 256, GEMM_SMEM>>>(
        p_ah, p_al, p_pb, out, CC, proj_b, 0);
}